// round 1
// baseline (speedup 1.0000x reference)
#include <cuda_runtime.h>
#include <math.h>

#define NN 50000
#define EE 800000
#define RR 2000
#define FF 128
#define LDP 2
#define FDIM 384
#define PP 64

// ---------------- scratch (device globals; no allocation allowed) ----------------
__device__ int   g_cnt[NN];
__device__ int   g_ptr[NN + 1];
__device__ int   g_cur[NN];
__device__ int   g_ssrc[EE];
__device__ int   g_srel[EE];
__device__ float g_relnorm[RR * FF];
__device__ float g_scores[2 * LDP * RR];          // [dual][layer][r]
__device__ float g_oute[(size_t)NN * FDIM];       // ent outputs (3 concatenated layers)
__device__ float g_outr[(size_t)NN * FDIM];       // rel outputs
__device__ float g_proxyn[2][PP * FDIM];          // l2-normalized proxy rows
__device__ float g_invn[2][NN];                   // 1/max(||outputs row||, eps)
__device__ float g_attw[(size_t)NN * PP];         // proxy attention (reused per dual)
__device__ float g_pf[(size_t)NN * FDIM];         // proxy_feature (reused per dual)

// ---------------- reduction helpers ----------------
__device__ __forceinline__ float warpSum(float v) {
#pragma unroll
    for (int o = 16; o; o >>= 1) v += __shfl_xor_sync(0xffffffffu, v, o);
    return v;
}
__device__ __forceinline__ float warpMax(float v) {
#pragma unroll
    for (int o = 16; o; o >>= 1) v = fmaxf(v, __shfl_xor_sync(0xffffffffu, v, o));
    return v;
}
// full-block sum, result broadcast to all threads. sh must hold >= 32 floats.
__device__ __forceinline__ float blockSum(float v, float* sh) {
    int lane = threadIdx.x & 31, w = threadIdx.x >> 5;
    v = warpSum(v);
    if (lane == 0) sh[w] = v;
    __syncthreads();
    if (threadIdx.x == 0) {
        int nw = (blockDim.x + 31) >> 5;
        float r = 0.f;
        for (int i = 0; i < nw; i++) r += sh[i];
        sh[0] = r;
    }
    __syncthreads();
    float r = sh[0];
    __syncthreads();
    return r;
}

// ---------------- CSR build ----------------
__global__ void k_zero() {
    int i = blockIdx.x * blockDim.x + threadIdx.x;
    if (i < NN) g_cnt[i] = 0;
}
__global__ void k_hist(const int* __restrict__ edst) {
    int e = blockIdx.x * blockDim.x + threadIdx.x;
    if (e < EE) atomicAdd(&g_cnt[edst[e]], 1);
}
__global__ void k_scan() {
    __shared__ int partial[1024];
    int tid = threadIdx.x;
    const int CH = 49;  // 1024*49 = 50176 >= NN
    int base = tid * CH;
    int s = 0;
    for (int i = 0; i < CH; i++) {
        int idx = base + i;
        if (idx < NN) s += g_cnt[idx];
    }
    partial[tid] = s;
    __syncthreads();
    for (int off = 1; off < 1024; off <<= 1) {
        int v = (tid >= off) ? partial[tid - off] : 0;
        __syncthreads();
        partial[tid] += v;
        __syncthreads();
    }
    int run = (tid == 0) ? 0 : partial[tid - 1];
    for (int i = 0; i < CH; i++) {
        int idx = base + i;
        if (idx < NN) {
            g_ptr[idx] = run;
            g_cur[idx] = run;
            run += g_cnt[idx];
        }
    }
    if (tid == 0) g_ptr[NN] = EE;
}
__global__ void k_scatter(const int* __restrict__ esrc, const int* __restrict__ edst,
                          const int* __restrict__ erel) {
    int e = blockIdx.x * blockDim.x + threadIdx.x;
    if (e < EE) {
        int d = edst[e];
        int p = atomicAdd(&g_cur[d], 1);
        g_ssrc[p] = esrc[e];
        g_srel[p] = erel[e];
    }
}

// ---------------- per-relation: l2norm rows + attention scores ----------------
__global__ void k_relnorm(const float* __restrict__ rel_emb,
                          const float* __restrict__ attn_e,
                          const float* __restrict__ attn_r) {
    __shared__ float sh[32];
    int r = blockIdx.x, t = threadIdx.x;
    float v = rel_emb[r * FF + t];
    float s = blockSum(v * v, sh);
    float inv = 1.f / fmaxf(sqrtf(s), 1e-12f);
    float rn = v * inv;
    g_relnorm[r * FF + t] = rn;
    float d0 = blockSum(rn * attn_e[t], sh);
    float d1 = blockSum(rn * attn_e[FF + t], sh);
    float d2 = blockSum(rn * attn_r[t], sh);
    float d3 = blockSum(rn * attn_r[FF + t], sh);
    if (t == 0) {
        g_scores[(0 * LDP + 0) * RR + r] = d0;
        g_scores[(0 * LDP + 1) * RR + r] = d1;
        g_scores[(1 * LDP + 0) * RR + r] = d2;
        g_scores[(1 * LDP + 1) * RR + r] = d3;
    }
}

// ---------------- l2norm proxy rows ----------------
__global__ void k_proxyn(const float* __restrict__ pe, const float* __restrict__ pr) {
    __shared__ float sh[32];
    int dual = blockIdx.x >> 6, p = blockIdx.x & 63, t = threadIdx.x;
    const float* src = dual ? pr : pe;
    float v = src[p * FDIM + t];
    float s = blockSum(v * v, sh);
    float inv = 1.f / fmaxf(sqrtf(s), 1e-12f);
    g_proxyn[dual][p * FDIM + t] = v * inv;
}

// ---------------- initial features: tanh(mean of neighbor emb) ----------------
__global__ void k_init(const float* __restrict__ ent, const float* __restrict__ rel) {
    int warp = threadIdx.x >> 5, lane = threadIdx.x & 31;
    int n = blockIdx.x * 8 + warp;
    if (n >= NN) return;
    int beg = g_ptr[n], end = g_ptr[n + 1];
    float4 ae = {0, 0, 0, 0}, ar = {0, 0, 0, 0};
    for (int i = beg; i < end; i++) {
        int s = g_ssrc[i], r = g_srel[i];
        float4 a = *(const float4*)&ent[(size_t)s * FF + lane * 4];
        float4 b = *(const float4*)&rel[(size_t)r * FF + lane * 4];
        ae.x += a.x; ae.y += a.y; ae.z += a.z; ae.w += a.w;
        ar.x += b.x; ar.y += b.y; ar.z += b.z; ar.w += b.w;
    }
    float inv = 1.f / fmaxf((float)(end - beg), 1.f);
    float* oe = g_oute + (size_t)n * FDIM + lane * 4;
    float* orr = g_outr + (size_t)n * FDIM + lane * 4;
    oe[0] = tanhf(ae.x * inv); oe[1] = tanhf(ae.y * inv);
    oe[2] = tanhf(ae.z * inv); oe[3] = tanhf(ae.w * inv);
    orr[0] = tanhf(ar.x * inv); orr[1] = tanhf(ar.y * inv);
    orr[2] = tanhf(ar.z * inv); orr[3] = tanhf(ar.w * inv);
}

// ---------------- GNN layer (both duals fused): softmax + Householder + agg ----------------
__global__ void k_layer(int l) {
    int warp = threadIdx.x >> 5, lane = threadIdx.x & 31;
    int n = blockIdx.x * 8 + warp;
    if (n >= NN) return;
    const float* sc_e = g_scores + (0 * LDP + l) * RR;
    const float* sc_r = g_scores + (1 * LDP + l) * RR;
    int beg = g_ptr[n], end = g_ptr[n + 1];

    // segment softmax stats (per-dst)
    float me = -3e38f, mr = -3e38f;
    for (int i = beg + lane; i < end; i += 32) {
        int r = g_srel[i];
        me = fmaxf(me, sc_e[r]);
        mr = fmaxf(mr, sc_r[r]);
    }
    me = warpMax(me); mr = warpMax(mr);
    float se = 0.f, sr = 0.f;
    for (int i = beg + lane; i < end; i += 32) {
        int r = g_srel[i];
        se += expf(sc_e[r] - me);
        sr += expf(sc_r[r] - mr);
    }
    se = warpSum(se); sr = warpSum(sr);
    float ise = (se > 0.f) ? 1.f / se : 0.f;
    float isr = (sr > 0.f) ? 1.f / sr : 0.f;

    float4 acce = {0, 0, 0, 0}, accr = {0, 0, 0, 0};
    int co = l * FF + lane * 4;
    for (int i = beg; i < end; i++) {
        int s = g_ssrc[i], r = g_srel[i];
        float we = expf(sc_e[r] - me) * ise;
        float wr = expf(sc_r[r] - mr) * isr;
        float4 rn = *(const float4*)&g_relnorm[r * FF + lane * 4];
        float4 fe = *(const float4*)&g_oute[(size_t)s * FDIM + co];
        float4 fr = *(const float4*)&g_outr[(size_t)s * FDIM + co];
        float de = fe.x * rn.x + fe.y * rn.y + fe.z * rn.z + fe.w * rn.w;
        float dr = fr.x * rn.x + fr.y * rn.y + fr.z * rn.z + fr.w * rn.w;
#pragma unroll
        for (int o = 16; o; o >>= 1) {
            de += __shfl_xor_sync(0xffffffffu, de, o);
            dr += __shfl_xor_sync(0xffffffffu, dr, o);
        }
        float ce = -2.f * de, cr = -2.f * dr;
        acce.x += we * (fe.x + ce * rn.x); acce.y += we * (fe.y + ce * rn.y);
        acce.z += we * (fe.z + ce * rn.z); acce.w += we * (fe.w + ce * rn.w);
        accr.x += wr * (fr.x + cr * rn.x); accr.y += wr * (fr.y + cr * rn.y);
        accr.z += wr * (fr.z + cr * rn.z); accr.w += wr * (fr.w + cr * rn.w);
    }
    float* oe = g_oute + (size_t)n * FDIM + (l + 1) * FF + lane * 4;
    float* orr = g_outr + (size_t)n * FDIM + (l + 1) * FF + lane * 4;
    oe[0] = tanhf(acce.x); oe[1] = tanhf(acce.y); oe[2] = tanhf(acce.z); oe[3] = tanhf(acce.w);
    orr[0] = tanhf(accr.x); orr[1] = tanhf(accr.y); orr[2] = tanhf(accr.z); orr[3] = tanhf(accr.w);
}

// ---------------- row inverse norms of outputs ----------------
__global__ void k_invnorm() {
    int w = blockIdx.x * 8 + (threadIdx.x >> 5);
    int lane = threadIdx.x & 31;
    if (w >= 2 * NN) return;
    int dual = w / NN, row = w % NN;
    const float* x = (dual ? g_outr : g_oute) + (size_t)row * FDIM;
    float s = 0.f;
#pragma unroll
    for (int k = 0; k < 3; k++) {
        float4 v = *(const float4*)&x[k * 128 + lane * 4];
        s += v.x * v.x + v.y * v.y + v.z * v.z + v.w * v.w;
    }
    s = warpSum(s);
    if (lane == 0) g_invn[dual][row] = 1.f / fmaxf(sqrtf(s), 1e-12f);
}

// ---------------- GEMM1: logits = (X @ proxyn^T)*invn, fused row softmax -> attw ----------------
__global__ void k_gemm1(int dual) {
    __shared__ float Ash[32][33];
    __shared__ float Bsh[32][65];
    __shared__ float Lsh[32][65];
    int mb = blockIdx.x * 32;
    const float* X = dual ? g_outr : g_oute;
    const float* Pn = g_proxyn[dual];
    int tid = threadIdx.x;
    int tx = tid & 31, ty = tid >> 5;  // ty 0..7
    float acc[4][2] = {};
    for (int kc = 0; kc < FDIM; kc += 32) {
        {
            int row = tid >> 3, kq = (tid & 7) * 4;
            float4 v = {0, 0, 0, 0};
            if (mb + row < NN) v = *(const float4*)&X[(size_t)(mb + row) * FDIM + kc + kq];
            Ash[row][kq] = v.x; Ash[row][kq + 1] = v.y;
            Ash[row][kq + 2] = v.z; Ash[row][kq + 3] = v.w;
        }
#pragma unroll
        for (int i = 0; i < 2; i++) {
            int li = tid + i * 256;
            int p = li >> 3, kq = (li & 7) * 4;
            float4 v = *(const float4*)&Pn[(size_t)p * FDIM + kc + kq];
            Bsh[kq][p] = v.x; Bsh[kq + 1][p] = v.y;
            Bsh[kq + 2][p] = v.z; Bsh[kq + 3][p] = v.w;
        }
        __syncthreads();
#pragma unroll
        for (int k = 0; k < 32; k++) {
            float b0 = Bsh[k][tx], b1 = Bsh[k][tx + 32];
#pragma unroll
            for (int i = 0; i < 4; i++) {
                float a = Ash[ty + 8 * i][k];
                acc[i][0] += a * b0;
                acc[i][1] += a * b1;
            }
        }
        __syncthreads();
    }
#pragma unroll
    for (int i = 0; i < 4; i++) {
        int row = ty + 8 * i;
        float inv = (mb + row < NN) ? g_invn[dual][mb + row] : 1.f;
        Lsh[row][tx] = acc[i][0] * inv;
        Lsh[row][tx + 32] = acc[i][1] * inv;
    }
    __syncthreads();
    if (tid < 32) {
        int g = mb + tid;
        if (g < NN) {
            float m = -3e38f;
            for (int c = 0; c < 64; c++) m = fmaxf(m, Lsh[tid][c]);
            float s = 0.f;
            for (int c = 0; c < 64; c++) s += expf(Lsh[tid][c] - m);
            float is = 1.f / s;
            for (int c = 0; c < 64; c++) g_attw[(size_t)g * PP + c] = expf(Lsh[tid][c] - m) * is;
        }
    }
}

// ---------------- GEMM2: pf = X - attw @ proxy ----------------
__global__ void k_gemm2(int dual, const float* __restrict__ proxy) {
    __shared__ float Ash[64][65];
    __shared__ float Bsh[64][68];
    int mb = blockIdx.x * 64, nb = blockIdx.y * 64;
    const float* X = dual ? g_outr : g_oute;
    int tid = threadIdx.x;
    int tx = tid & 15, ty = tid >> 4;
#pragma unroll
    for (int i = 0; i < 4; i++) {
        int li = tid + i * 256;
        int row = li >> 4, kq = (li & 15) * 4;
        float4 v = {0, 0, 0, 0};
        if (mb + row < NN) v = *(const float4*)&g_attw[(size_t)(mb + row) * PP + kq];
        Ash[row][kq] = v.x; Ash[row][kq + 1] = v.y;
        Ash[row][kq + 2] = v.z; Ash[row][kq + 3] = v.w;
    }
#pragma unroll
    for (int i = 0; i < 4; i++) {
        int li = tid + i * 256;
        int p = li >> 4, cq = (li & 15) * 4;
        float4 v = *(const float4*)&proxy[(size_t)p * FDIM + nb + cq];
        Bsh[p][cq] = v.x; Bsh[p][cq + 1] = v.y;
        Bsh[p][cq + 2] = v.z; Bsh[p][cq + 3] = v.w;
    }
    __syncthreads();
    float acc[4][4] = {};
#pragma unroll
    for (int k = 0; k < 64; k++) {
        float a[4], b[4];
#pragma unroll
        for (int i = 0; i < 4; i++) a[i] = Ash[ty * 4 + i][k];
#pragma unroll
        for (int j = 0; j < 4; j++) b[j] = Bsh[k][tx * 4 + j];
#pragma unroll
        for (int i = 0; i < 4; i++)
#pragma unroll
            for (int j = 0; j < 4; j++) acc[i][j] += a[i] * b[j];
    }
#pragma unroll
    for (int i = 0; i < 4; i++) {
        int row = mb + ty * 4 + i;
        if (row < NN) {
#pragma unroll
            for (int j = 0; j < 4; j++) {
                int col = nb + tx * 4 + j;
                g_pf[(size_t)row * FDIM + col] = X[(size_t)row * FDIM + col] - acc[i][j];
            }
        }
    }
}

// ---------------- GEMM3: gate = sigmoid(pf@G + b); out = gate*X + (1-gate)*pf ----------------
__global__ void k_gemm3(int dual, const float* __restrict__ G, const float* __restrict__ bias,
                        float* __restrict__ out) {
    __shared__ float Ash[16][132];
    __shared__ float Bsh[16][68];
    int mb = blockIdx.x * 128, nb = blockIdx.y * 64;
    const float* X = dual ? g_outr : g_oute;
    int tid = threadIdx.x;
    int tx = tid & 15, ty = tid >> 4;
    float acc[8][4] = {};
    for (int kc = 0; kc < FDIM; kc += 16) {
#pragma unroll
        for (int i = 0; i < 2; i++) {
            int li = tid + i * 256;      // 512 float4 slots: 128 rows x 4
            int row = li >> 2, kq = (li & 3) * 4;
            float4 v = {0, 0, 0, 0};
            if (mb + row < NN) v = *(const float4*)&g_pf[(size_t)(mb + row) * FDIM + kc + kq];
            Ash[kq][row] = v.x; Ash[kq + 1][row] = v.y;
            Ash[kq + 2][row] = v.z; Ash[kq + 3][row] = v.w;
        }
        {
            int k = tid >> 4, cq = (tid & 15) * 4;
            float4 v = *(const float4*)&G[(size_t)(kc + k) * FDIM + nb + cq];
            Bsh[k][cq] = v.x; Bsh[k][cq + 1] = v.y;
            Bsh[k][cq + 2] = v.z; Bsh[k][cq + 3] = v.w;
        }
        __syncthreads();
#pragma unroll
        for (int k = 0; k < 16; k++) {
            float b[4], a[8];
#pragma unroll
            for (int j = 0; j < 4; j++) b[j] = Bsh[k][tx * 4 + j];
#pragma unroll
            for (int i = 0; i < 8; i++) a[i] = Ash[k][ty * 8 + i];
#pragma unroll
            for (int i = 0; i < 8; i++)
#pragma unroll
                for (int j = 0; j < 4; j++) acc[i][j] += a[i] * b[j];
        }
        __syncthreads();
    }
#pragma unroll
    for (int i = 0; i < 8; i++) {
        int row = mb + ty * 8 + i;
        if (row < NN) {
#pragma unroll
            for (int j = 0; j < 4; j++) {
                int col = nb + tx * 4 + j;
                float gte = 1.f / (1.f + expf(-(acc[i][j] + bias[col])));
                float x = X[(size_t)row * FDIM + col];
                float p = g_pf[(size_t)row * FDIM + col];
                out[(size_t)row * (2 * FDIM) + dual * FDIM + col] = gte * x + (1.f - gte) * p;
            }
        }
    }
}

// ---------------- launch ----------------
extern "C" void kernel_launch(void* const* d_in, const int* in_sizes, int n_in,
                              void* d_out, int out_size) {
    const float* ent     = (const float*)d_in[0];
    const float* rel     = (const float*)d_in[1];
    const int*   esrc    = (const int*)d_in[2];
    const int*   edst    = (const int*)d_in[3];
    const int*   erel    = (const int*)d_in[4];
    const float* attn_e  = (const float*)d_in[5];
    const float* gate_e  = (const float*)d_in[6];
    const float* proxy_e = (const float*)d_in[7];
    const float* bias_e  = (const float*)d_in[8];
    const float* attn_r  = (const float*)d_in[9];
    const float* gate_r  = (const float*)d_in[10];
    const float* proxy_r = (const float*)d_in[11];
    const float* bias_r  = (const float*)d_in[12];
    float* out = (float*)d_out;

    k_zero<<<196, 256>>>();
    k_hist<<<3125, 256>>>(edst);
    k_scan<<<1, 1024>>>();
    k_scatter<<<3125, 256>>>(esrc, edst, erel);
    k_relnorm<<<RR, FF>>>(rel, attn_e, attn_r);
    k_proxyn<<<128, FDIM>>>(proxy_e, proxy_r);
    k_init<<<6250, 256>>>(ent, rel);
    k_layer<<<6250, 256>>>(0);
    k_layer<<<6250, 256>>>(1);
    k_invnorm<<<12500, 256>>>();
    for (int d = 0; d < 2; d++) {
        const float* prox = d ? proxy_r : proxy_e;
        const float* G    = d ? gate_r : gate_e;
        const float* bias = d ? bias_r : bias_e;
        k_gemm1<<<1563, 256>>>(d);
        k_gemm2<<<dim3(782, 6), 256>>>(d, prox);
        k_gemm3<<<dim3(391, 6), 256>>>(d, G, bias, out);
    }
}

// round 2
// speedup vs baseline: 1.5689x; 1.5689x over previous
#include <cuda_runtime.h>
#include <math.h>

#define NN 50000
#define EE 800000
#define RR 2000
#define FF 128
#define LDP 2
#define FDIM 384
#define PP 64

// ---------------- scratch (device globals; no allocation allowed) ----------------
__device__ int   g_cnt[NN];
__device__ int   g_ptr[NN + 1];
__device__ int   g_cur[NN];
__device__ int   g_ssrc[EE];
__device__ int   g_srel[EE];
__device__ float g_relnorm[RR * FF];
__device__ float g_scores[2 * LDP * RR];          // [dual][layer][r]
__device__ float g_oute[(size_t)NN * FDIM];       // ent outputs (3 concatenated layers)
__device__ float g_outr[(size_t)NN * FDIM];       // rel outputs
__device__ float g_proxynT[2][FDIM * PP];         // l2-normalized proxy rows, TRANSPOSED [k][p]
__device__ float g_invn[2][NN];                   // 1/max(||outputs row||, eps)
__device__ float g_attw[(size_t)NN * PP];         // proxy attention (reused per dual)
__device__ float g_pf[(size_t)NN * FDIM];         // proxy_feature (reused per dual)

// ---------------- helpers ----------------
__device__ __forceinline__ float warpSum(float v) {
#pragma unroll
    for (int o = 16; o; o >>= 1) v += __shfl_xor_sync(0xffffffffu, v, o);
    return v;
}
__device__ __forceinline__ float warpMax(float v) {
#pragma unroll
    for (int o = 16; o; o >>= 1) v = fmaxf(v, __shfl_xor_sync(0xffffffffu, v, o));
    return v;
}
__device__ __forceinline__ float blockSum(float v, float* sh) {
    int lane = threadIdx.x & 31, w = threadIdx.x >> 5;
    v = warpSum(v);
    if (lane == 0) sh[w] = v;
    __syncthreads();
    if (threadIdx.x == 0) {
        int nw = (blockDim.x + 31) >> 5;
        float r = 0.f;
        for (int i = 0; i < nw; i++) r += sh[i];
        sh[0] = r;
    }
    __syncthreads();
    float r = sh[0];
    __syncthreads();
    return r;
}

__device__ __forceinline__ unsigned f2tf(float x) {
    unsigned r;
    asm("cvt.rna.tf32.f32 %0, %1;" : "=r"(r) : "f"(x));
    return r;
}
__device__ __forceinline__ void mma_tf32(float* c, const unsigned* a, const unsigned* b) {
    asm volatile(
        "mma.sync.aligned.m16n8k8.row.col.f32.tf32.tf32.f32 "
        "{%0,%1,%2,%3}, {%4,%5,%6,%7}, {%8,%9}, {%0,%1,%2,%3};"
        : "+f"(c[0]), "+f"(c[1]), "+f"(c[2]), "+f"(c[3])
        : "r"(a[0]), "r"(a[1]), "r"(a[2]), "r"(a[3]), "r"(b[0]), "r"(b[1]));
}

// ---------------- CSR build ----------------
__global__ void k_zero() {
    int i = blockIdx.x * blockDim.x + threadIdx.x;
    if (i < NN) g_cnt[i] = 0;
}
__global__ void k_hist(const int* __restrict__ edst) {
    int e = blockIdx.x * blockDim.x + threadIdx.x;
    if (e < EE) atomicAdd(&g_cnt[edst[e]], 1);
}
__global__ void k_scan() {
    __shared__ int partial[1024];
    int tid = threadIdx.x;
    const int CH = 49;
    int base = tid * CH;
    int s = 0;
    for (int i = 0; i < CH; i++) {
        int idx = base + i;
        if (idx < NN) s += g_cnt[idx];
    }
    partial[tid] = s;
    __syncthreads();
    for (int off = 1; off < 1024; off <<= 1) {
        int v = (tid >= off) ? partial[tid - off] : 0;
        __syncthreads();
        partial[tid] += v;
        __syncthreads();
    }
    int run = (tid == 0) ? 0 : partial[tid - 1];
    for (int i = 0; i < CH; i++) {
        int idx = base + i;
        if (idx < NN) {
            g_ptr[idx] = run;
            g_cur[idx] = run;
            run += g_cnt[idx];
        }
    }
    if (tid == 0) g_ptr[NN] = EE;
}
__global__ void k_scatter(const int* __restrict__ esrc, const int* __restrict__ edst,
                          const int* __restrict__ erel) {
    int e = blockIdx.x * blockDim.x + threadIdx.x;
    if (e < EE) {
        int d = edst[e];
        int p = atomicAdd(&g_cur[d], 1);
        g_ssrc[p] = esrc[e];
        g_srel[p] = erel[e];
    }
}

// ---------------- per-relation: l2norm rows + attention scores ----------------
__global__ void k_relnorm(const float* __restrict__ rel_emb,
                          const float* __restrict__ attn_e,
                          const float* __restrict__ attn_r) {
    __shared__ float sh[32];
    int r = blockIdx.x, t = threadIdx.x;
    float v = rel_emb[r * FF + t];
    float s = blockSum(v * v, sh);
    float inv = 1.f / fmaxf(sqrtf(s), 1e-12f);
    float rn = v * inv;
    g_relnorm[r * FF + t] = rn;
    float d0 = blockSum(rn * attn_e[t], sh);
    float d1 = blockSum(rn * attn_e[FF + t], sh);
    float d2 = blockSum(rn * attn_r[t], sh);
    float d3 = blockSum(rn * attn_r[FF + t], sh);
    if (t == 0) {
        g_scores[(0 * LDP + 0) * RR + r] = d0;
        g_scores[(0 * LDP + 1) * RR + r] = d1;
        g_scores[(1 * LDP + 0) * RR + r] = d2;
        g_scores[(1 * LDP + 1) * RR + r] = d3;
    }
}

// ---------------- l2norm proxy rows (stored transposed for tensor GEMM) ----------------
__global__ void k_proxyn(const float* __restrict__ pe, const float* __restrict__ pr) {
    __shared__ float sh[32];
    int dual = blockIdx.x >> 6, p = blockIdx.x & 63, t = threadIdx.x;
    const float* src = dual ? pr : pe;
    float v = src[p * FDIM + t];
    float s = blockSum(v * v, sh);
    float inv = 1.f / fmaxf(sqrtf(s), 1e-12f);
    g_proxynT[dual][t * PP + p] = v * inv;
}

// ---------------- initial features: tanh(mean of neighbor emb) ----------------
__global__ void k_init(const float* __restrict__ ent, const float* __restrict__ rel) {
    int warp = threadIdx.x >> 5, lane = threadIdx.x & 31;
    int n = blockIdx.x * 8 + warp;
    if (n >= NN) return;
    int beg = g_ptr[n], end = g_ptr[n + 1];
    float4 ae = {0, 0, 0, 0}, ar = {0, 0, 0, 0};
    for (int i = beg; i < end; i++) {
        int s = g_ssrc[i], r = g_srel[i];
        float4 a = *(const float4*)&ent[(size_t)s * FF + lane * 4];
        float4 b = *(const float4*)&rel[(size_t)r * FF + lane * 4];
        ae.x += a.x; ae.y += a.y; ae.z += a.z; ae.w += a.w;
        ar.x += b.x; ar.y += b.y; ar.z += b.z; ar.w += b.w;
    }
    float inv = 1.f / fmaxf((float)(end - beg), 1.f);
    float* oe = g_oute + (size_t)n * FDIM + lane * 4;
    float* orr = g_outr + (size_t)n * FDIM + lane * 4;
    oe[0] = tanhf(ae.x * inv); oe[1] = tanhf(ae.y * inv);
    oe[2] = tanhf(ae.z * inv); oe[3] = tanhf(ae.w * inv);
    orr[0] = tanhf(ar.x * inv); orr[1] = tanhf(ar.y * inv);
    orr[2] = tanhf(ar.z * inv); orr[3] = tanhf(ar.w * inv);
}

// ---------------- GNN layer (both duals fused) ----------------
__global__ void k_layer(int l) {
    int warp = threadIdx.x >> 5, lane = threadIdx.x & 31;
    int n = blockIdx.x * 8 + warp;
    if (n >= NN) return;
    const float* sc_e = g_scores + (0 * LDP + l) * RR;
    const float* sc_r = g_scores + (1 * LDP + l) * RR;
    int beg = g_ptr[n], end = g_ptr[n + 1];

    float me = -3e38f, mr = -3e38f;
    for (int i = beg + lane; i < end; i += 32) {
        int r = g_srel[i];
        me = fmaxf(me, sc_e[r]);
        mr = fmaxf(mr, sc_r[r]);
    }
    me = warpMax(me); mr = warpMax(mr);
    float se = 0.f, sr = 0.f;
    for (int i = beg + lane; i < end; i += 32) {
        int r = g_srel[i];
        se += expf(sc_e[r] - me);
        sr += expf(sc_r[r] - mr);
    }
    se = warpSum(se); sr = warpSum(sr);
    float ise = (se > 0.f) ? 1.f / se : 0.f;
    float isr = (sr > 0.f) ? 1.f / sr : 0.f;

    float4 acce = {0, 0, 0, 0}, accr = {0, 0, 0, 0};
    int co = l * FF + lane * 4;
    for (int i = beg; i < end; i++) {
        int s = g_ssrc[i], r = g_srel[i];
        float we = expf(sc_e[r] - me) * ise;
        float wr = expf(sc_r[r] - mr) * isr;
        float4 rn = *(const float4*)&g_relnorm[r * FF + lane * 4];
        float4 fe = *(const float4*)&g_oute[(size_t)s * FDIM + co];
        float4 fr = *(const float4*)&g_outr[(size_t)s * FDIM + co];
        float de = fe.x * rn.x + fe.y * rn.y + fe.z * rn.z + fe.w * rn.w;
        float dr = fr.x * rn.x + fr.y * rn.y + fr.z * rn.z + fr.w * rn.w;
#pragma unroll
        for (int o = 16; o; o >>= 1) {
            de += __shfl_xor_sync(0xffffffffu, de, o);
            dr += __shfl_xor_sync(0xffffffffu, dr, o);
        }
        float ce = -2.f * de, cr = -2.f * dr;
        acce.x += we * (fe.x + ce * rn.x); acce.y += we * (fe.y + ce * rn.y);
        acce.z += we * (fe.z + ce * rn.z); acce.w += we * (fe.w + ce * rn.w);
        accr.x += wr * (fr.x + cr * rn.x); accr.y += wr * (fr.y + cr * rn.y);
        accr.z += wr * (fr.z + cr * rn.z); accr.w += wr * (fr.w + cr * rn.w);
    }
    float* oe = g_oute + (size_t)n * FDIM + (l + 1) * FF + lane * 4;
    float* orr = g_outr + (size_t)n * FDIM + (l + 1) * FF + lane * 4;
    oe[0] = tanhf(acce.x); oe[1] = tanhf(acce.y); oe[2] = tanhf(acce.z); oe[3] = tanhf(acce.w);
    orr[0] = tanhf(accr.x); orr[1] = tanhf(accr.y); orr[2] = tanhf(accr.z); orr[3] = tanhf(accr.w);
}

// ---------------- row inverse norms of outputs ----------------
__global__ void k_invnorm() {
    int w = blockIdx.x * 8 + (threadIdx.x >> 5);
    int lane = threadIdx.x & 31;
    if (w >= 2 * NN) return;
    int dual = w / NN, row = w % NN;
    const float* x = (dual ? g_outr : g_oute) + (size_t)row * FDIM;
    float s = 0.f;
#pragma unroll
    for (int k = 0; k < 3; k++) {
        float4 v = *(const float4*)&x[k * 128 + lane * 4];
        s += v.x * v.x + v.y * v.y + v.z * v.z + v.w * v.w;
    }
    s = warpSum(s);
    if (lane == 0) g_invn[dual][row] = 1.f / fmaxf(sqrtf(s), 1e-12f);
}

// ================= tensor-core (tf32 mma) GEMMs =================
// Fragment layout m16n8k8 (row.col):
//  A: a0=[g][t] a1=[g+8][t] a2=[g][t+4] a3=[g+8][t+4]   (g=lane>>2, t=lane&3)
//  B: b0=[t][g] b1=[t+4][g]
//  C: c0=[g][2t] c1=[g][2t+1] c2=[g+8][2t] c3=[g+8][2t+1]

// GEMM1: logits = invn * (X @ proxynT) fused row-softmax -> g_attw. BM=128, BN=64(=PP), BK=32.
__global__ __launch_bounds__(256) void k_gemm1t(int dual) {
    __shared__ union {
        struct { unsigned As[128][36]; unsigned Bs[32][72]; } s;
        float Ls[128][66];
    } u;
    int mb = blockIdx.x * 128;
    const float* X = dual ? g_outr : g_oute;
    const float* BT = g_proxynT[dual];
    int tid = threadIdx.x, lane = tid & 31, wid = tid >> 5;
    int g = lane >> 2, t4 = lane & 3;
    int warpM = wid * 16;
    float acc[8][4] = {};
    for (int kc = 0; kc < FDIM; kc += 32) {
#pragma unroll
        for (int i = 0; i < 4; i++) {
            int id = tid + i * 256;
            int row = id >> 3, kq = (id & 7) * 4;
            float4 v = {0, 0, 0, 0};
            if (mb + row < NN) v = *(const float4*)&X[(size_t)(mb + row) * FDIM + kc + kq];
            u.s.As[row][kq] = f2tf(v.x); u.s.As[row][kq + 1] = f2tf(v.y);
            u.s.As[row][kq + 2] = f2tf(v.z); u.s.As[row][kq + 3] = f2tf(v.w);
        }
#pragma unroll
        for (int i = 0; i < 2; i++) {
            int id = tid + i * 256;  // 512 float4: 32 k-rows x 16
            int k = id >> 4, cq = (id & 15) * 4;
            float4 v = *(const float4*)&BT[(size_t)(kc + k) * PP + cq];
            u.s.Bs[k][cq] = f2tf(v.x); u.s.Bs[k][cq + 1] = f2tf(v.y);
            u.s.Bs[k][cq + 2] = f2tf(v.z); u.s.Bs[k][cq + 3] = f2tf(v.w);
        }
        __syncthreads();
#pragma unroll
        for (int ks = 0; ks < 4; ks++) {
            int k0 = ks * 8;
            unsigned a[4], b[8][2];
            a[0] = u.s.As[warpM + g][k0 + t4];
            a[1] = u.s.As[warpM + g + 8][k0 + t4];
            a[2] = u.s.As[warpM + g][k0 + t4 + 4];
            a[3] = u.s.As[warpM + g + 8][k0 + t4 + 4];
#pragma unroll
            for (int nt = 0; nt < 8; nt++) {
                b[nt][0] = u.s.Bs[k0 + t4][nt * 8 + g];
                b[nt][1] = u.s.Bs[k0 + t4 + 4][nt * 8 + g];
            }
#pragma unroll
            for (int nt = 0; nt < 8; nt++) mma_tf32(acc[nt], a, b[nt]);
        }
        __syncthreads();
    }
    // write scaled logits to smem
#pragma unroll
    for (int nt = 0; nt < 8; nt++) {
        int r0 = warpM + g, r1 = warpM + g + 8, c0 = nt * 8 + t4 * 2;
        float i0 = (mb + r0 < NN) ? g_invn[dual][mb + r0] : 1.f;
        float i1 = (mb + r1 < NN) ? g_invn[dual][mb + r1] : 1.f;
        u.Ls[r0][c0] = acc[nt][0] * i0; u.Ls[r0][c0 + 1] = acc[nt][1] * i0;
        u.Ls[r1][c0] = acc[nt][2] * i1; u.Ls[r1][c0 + 1] = acc[nt][3] * i1;
    }
    __syncthreads();
    if (tid < 128) {
        int gn = mb + tid;
        if (gn < NN) {
            float m = -3e38f;
            for (int c = 0; c < PP; c++) m = fmaxf(m, u.Ls[tid][c]);
            float s = 0.f;
            for (int c = 0; c < PP; c++) s += expf(u.Ls[tid][c] - m);
            float is = 1.f / s;
            for (int c = 0; c < PP; c++)
                g_attw[(size_t)gn * PP + c] = expf(u.Ls[tid][c] - m) * is;
        }
    }
}

// GEMM2: pf = X - attw @ proxy. BM=128, BN=128, BK=32, K=64.
__global__ __launch_bounds__(256) void k_gemm2t(int dual, const float* __restrict__ proxy) {
    __shared__ unsigned As[128][36];
    __shared__ unsigned Bs[32][136];
    int mb = blockIdx.x * 128, nb = blockIdx.y * 128;
    const float* X = dual ? g_outr : g_oute;
    int tid = threadIdx.x, lane = tid & 31, wid = tid >> 5;
    int g = lane >> 2, t4 = lane & 3;
    int warpM = (wid & 3) * 32, warpN = (wid >> 2) * 64;
    float acc[2][8][4] = {};
    for (int kc = 0; kc < PP; kc += 32) {
#pragma unroll
        for (int i = 0; i < 4; i++) {
            int id = tid + i * 256;
            int row = id >> 3, kq = (id & 7) * 4;
            float4 v = {0, 0, 0, 0};
            if (mb + row < NN) v = *(const float4*)&g_attw[(size_t)(mb + row) * PP + kc + kq];
            As[row][kq] = f2tf(v.x); As[row][kq + 1] = f2tf(v.y);
            As[row][kq + 2] = f2tf(v.z); As[row][kq + 3] = f2tf(v.w);
        }
#pragma unroll
        for (int i = 0; i < 4; i++) {
            int id = tid + i * 256;
            int k = id >> 5, cq = (id & 31) * 4;
            float4 v = *(const float4*)&proxy[(size_t)(kc + k) * FDIM + nb + cq];
            Bs[k][cq] = f2tf(v.x); Bs[k][cq + 1] = f2tf(v.y);
            Bs[k][cq + 2] = f2tf(v.z); Bs[k][cq + 3] = f2tf(v.w);
        }
        __syncthreads();
#pragma unroll
        for (int ks = 0; ks < 4; ks++) {
            int k0 = ks * 8;
            unsigned a[2][4], b[8][2];
#pragma unroll
            for (int mt = 0; mt < 2; mt++) {
                int r = warpM + mt * 16;
                a[mt][0] = As[r + g][k0 + t4];
                a[mt][1] = As[r + g + 8][k0 + t4];
                a[mt][2] = As[r + g][k0 + t4 + 4];
                a[mt][3] = As[r + g + 8][k0 + t4 + 4];
            }
#pragma unroll
            for (int nt = 0; nt < 8; nt++) {
                b[nt][0] = Bs[k0 + t4][warpN + nt * 8 + g];
                b[nt][1] = Bs[k0 + t4 + 4][warpN + nt * 8 + g];
            }
#pragma unroll
            for (int mt = 0; mt < 2; mt++)
#pragma unroll
                for (int nt = 0; nt < 8; nt++) mma_tf32(acc[mt][nt], a[mt], b[nt]);
        }
        __syncthreads();
    }
#pragma unroll
    for (int mt = 0; mt < 2; mt++) {
#pragma unroll
        for (int nt = 0; nt < 8; nt++) {
            int col = nb + warpN + nt * 8 + t4 * 2;
            int r0 = mb + warpM + mt * 16 + g, r1 = r0 + 8;
            if (r0 < NN) {
                float2 x = *(const float2*)&X[(size_t)r0 * FDIM + col];
                float2 o = {x.x - acc[mt][nt][0], x.y - acc[mt][nt][1]};
                *(float2*)&g_pf[(size_t)r0 * FDIM + col] = o;
            }
            if (r1 < NN) {
                float2 x = *(const float2*)&X[(size_t)r1 * FDIM + col];
                float2 o = {x.x - acc[mt][nt][2], x.y - acc[mt][nt][3]};
                *(float2*)&g_pf[(size_t)r1 * FDIM + col] = o;
            }
        }
    }
}

// GEMM3: gate = sigmoid(pf@G + b); out = gate*X + (1-gate)*pf. BM=128, BN=128, BK=32, K=384.
__global__ __launch_bounds__(256) void k_gemm3t(int dual, const float* __restrict__ G,
                                                const float* __restrict__ bias,
                                                float* __restrict__ out) {
    __shared__ unsigned As[128][36];
    __shared__ unsigned Bs[32][136];
    int mb = blockIdx.x * 128, nb = blockIdx.y * 128;
    const float* X = dual ? g_outr : g_oute;
    int tid = threadIdx.x, lane = tid & 31, wid = tid >> 5;
    int g = lane >> 2, t4 = lane & 3;
    int warpM = (wid & 3) * 32, warpN = (wid >> 2) * 64;
    float acc[2][8][4] = {};
    for (int kc = 0; kc < FDIM; kc += 32) {
#pragma unroll
        for (int i = 0; i < 4; i++) {
            int id = tid + i * 256;
            int row = id >> 3, kq = (id & 7) * 4;
            float4 v = {0, 0, 0, 0};
            if (mb + row < NN) v = *(const float4*)&g_pf[(size_t)(mb + row) * FDIM + kc + kq];
            As[row][kq] = f2tf(v.x); As[row][kq + 1] = f2tf(v.y);
            As[row][kq + 2] = f2tf(v.z); As[row][kq + 3] = f2tf(v.w);
        }
#pragma unroll
        for (int i = 0; i < 4; i++) {
            int id = tid + i * 256;
            int k = id >> 5, cq = (id & 31) * 4;
            float4 v = *(const float4*)&G[(size_t)(kc + k) * FDIM + nb + cq];
            Bs[k][cq] = f2tf(v.x); Bs[k][cq + 1] = f2tf(v.y);
            Bs[k][cq + 2] = f2tf(v.z); Bs[k][cq + 3] = f2tf(v.w);
        }
        __syncthreads();
#pragma unroll
        for (int ks = 0; ks < 4; ks++) {
            int k0 = ks * 8;
            unsigned a[2][4], b[8][2];
#pragma unroll
            for (int mt = 0; mt < 2; mt++) {
                int r = warpM + mt * 16;
                a[mt][0] = As[r + g][k0 + t4];
                a[mt][1] = As[r + g + 8][k0 + t4];
                a[mt][2] = As[r + g][k0 + t4 + 4];
                a[mt][3] = As[r + g + 8][k0 + t4 + 4];
            }
#pragma unroll
            for (int nt = 0; nt < 8; nt++) {
                b[nt][0] = Bs[k0 + t4][warpN + nt * 8 + g];
                b[nt][1] = Bs[k0 + t4 + 4][warpN + nt * 8 + g];
            }
#pragma unroll
            for (int mt = 0; mt < 2; mt++)
#pragma unroll
                for (int nt = 0; nt < 8; nt++) mma_tf32(acc[mt][nt], a[mt], b[nt]);
        }
        __syncthreads();
    }
#pragma unroll
    for (int mt = 0; mt < 2; mt++) {
#pragma unroll
        for (int nt = 0; nt < 8; nt++) {
            int col = nb + warpN + nt * 8 + t4 * 2;
            float b0 = bias[col], b1 = bias[col + 1];
            int r0 = mb + warpM + mt * 16 + g, r1 = r0 + 8;
            if (r0 < NN) {
                float g0 = 1.f / (1.f + expf(-(acc[mt][nt][0] + b0)));
                float g1 = 1.f / (1.f + expf(-(acc[mt][nt][1] + b1)));
                float2 x = *(const float2*)&X[(size_t)r0 * FDIM + col];
                float2 p = *(const float2*)&g_pf[(size_t)r0 * FDIM + col];
                float2 o = {g0 * x.x + (1.f - g0) * p.x, g1 * x.y + (1.f - g1) * p.y};
                *(float2*)&out[(size_t)r0 * (2 * FDIM) + dual * FDIM + col] = o;
            }
            if (r1 < NN) {
                float g0 = 1.f / (1.f + expf(-(acc[mt][nt][2] + b0)));
                float g1 = 1.f / (1.f + expf(-(acc[mt][nt][3] + b1)));
                float2 x = *(const float2*)&X[(size_t)r1 * FDIM + col];
                float2 p = *(const float2*)&g_pf[(size_t)r1 * FDIM + col];
                float2 o = {g0 * x.x + (1.f - g0) * p.x, g1 * x.y + (1.f - g1) * p.y};
                *(float2*)&out[(size_t)r1 * (2 * FDIM) + dual * FDIM + col] = o;
            }
        }
    }
}

// ---------------- launch ----------------
extern "C" void kernel_launch(void* const* d_in, const int* in_sizes, int n_in,
                              void* d_out, int out_size) {
    const float* ent     = (const float*)d_in[0];
    const float* rel     = (const float*)d_in[1];
    const int*   esrc    = (const int*)d_in[2];
    const int*   edst    = (const int*)d_in[3];
    const int*   erel    = (const int*)d_in[4];
    const float* attn_e  = (const float*)d_in[5];
    const float* gate_e  = (const float*)d_in[6];
    const float* proxy_e = (const float*)d_in[7];
    const float* bias_e  = (const float*)d_in[8];
    const float* attn_r  = (const float*)d_in[9];
    const float* gate_r  = (const float*)d_in[10];
    const float* proxy_r = (const float*)d_in[11];
    const float* bias_r  = (const float*)d_in[12];
    float* out = (float*)d_out;

    k_zero<<<196, 256>>>();
    k_hist<<<3125, 256>>>(edst);
    k_scan<<<1, 1024>>>();
    k_scatter<<<3125, 256>>>(esrc, edst, erel);
    k_relnorm<<<RR, FF>>>(rel, attn_e, attn_r);
    k_proxyn<<<128, FDIM>>>(proxy_e, proxy_r);
    k_init<<<6250, 256>>>(ent, rel);
    k_layer<<<6250, 256>>>(0);
    k_layer<<<6250, 256>>>(1);
    k_invnorm<<<12500, 256>>>();
    for (int d = 0; d < 2; d++) {
        const float* prox = d ? proxy_r : proxy_e;
        const float* G    = d ? gate_r : gate_e;
        const float* bias = d ? bias_r : bias_e;
        k_gemm1t<<<391, 256>>>(d);
        k_gemm2t<<<dim3(391, 3), 256>>>(d, prox);
        k_gemm3t<<<dim3(391, 3), 256>>>(d, G, bias, out);
    }
}

// round 3
// speedup vs baseline: 1.5867x; 1.0113x over previous
#include <cuda_runtime.h>
#include <math.h>

#define NN 50000
#define EE 800000
#define RR 2000
#define FF 128
#define LDP 2
#define FDIM 384
#define PP 64

// ---------------- scratch (device globals; no allocation allowed) ----------------
__device__ int   g_cnt[NN];
__device__ int   g_ptr[NN + 1];
__device__ int   g_cur[NN];
__device__ int   g_ssrc[EE];
__device__ int   g_srel[EE];
__device__ float g_relnorm[RR * FF];
__device__ float g_exps[2 * LDP * RR];            // exp(score) [dual][layer][r]
__device__ float g_oute[(size_t)NN * FDIM];
__device__ float g_outr[(size_t)NN * FDIM];
__device__ float g_proxynT[2][FDIM * PP];         // l2-normed proxy, transposed [k][p]
__device__ float g_invn[2][NN];
__device__ float g_attw[(size_t)2 * NN * PP];     // per-dual proxy attention
__device__ float g_pf[(size_t)2 * NN * FDIM];     // per-dual proxy_feature

// ---------------- helpers ----------------
__device__ __forceinline__ float warpSum(float v) {
#pragma unroll
    for (int o = 16; o; o >>= 1) v += __shfl_xor_sync(0xffffffffu, v, o);
    return v;
}
__device__ __forceinline__ float blockSum(float v, float* sh) {
    int lane = threadIdx.x & 31, w = threadIdx.x >> 5;
    v = warpSum(v);
    if (lane == 0) sh[w] = v;
    __syncthreads();
    if (threadIdx.x == 0) {
        int nw = (blockDim.x + 31) >> 5;
        float r = 0.f;
        for (int i = 0; i < nw; i++) r += sh[i];
        sh[0] = r;
    }
    __syncthreads();
    float r = sh[0];
    __syncthreads();
    return r;
}
__device__ __forceinline__ unsigned f2tf(float x) {
    unsigned r;
    asm("cvt.rna.tf32.f32 %0, %1;" : "=r"(r) : "f"(x));
    return r;
}
__device__ __forceinline__ void mma_tf32(float* c, const unsigned* a, const unsigned* b) {
    asm volatile(
        "mma.sync.aligned.m16n8k8.row.col.f32.tf32.tf32.f32 "
        "{%0,%1,%2,%3}, {%4,%5,%6,%7}, {%8,%9}, {%0,%1,%2,%3};"
        : "+f"(c[0]), "+f"(c[1]), "+f"(c[2]), "+f"(c[3])
        : "r"(a[0]), "r"(a[1]), "r"(a[2]), "r"(a[3]), "r"(b[0]), "r"(b[1]));
}

// ---------------- CSR build ----------------
__global__ void k_zero() {
    int i = blockIdx.x * blockDim.x + threadIdx.x;
    if (i < NN) g_cnt[i] = 0;
}
__global__ void k_hist(const int* __restrict__ edst) {
    int e = blockIdx.x * blockDim.x + threadIdx.x;
    if (e < EE) atomicAdd(&g_cnt[edst[e]], 1);
}
__global__ void k_scan() {
    __shared__ int partial[1024];
    int tid = threadIdx.x;
    const int CH = 49;
    int base = tid * CH;
    int s = 0;
    for (int i = 0; i < CH; i++) {
        int idx = base + i;
        if (idx < NN) s += g_cnt[idx];
    }
    partial[tid] = s;
    __syncthreads();
    for (int off = 1; off < 1024; off <<= 1) {
        int v = (tid >= off) ? partial[tid - off] : 0;
        __syncthreads();
        partial[tid] += v;
        __syncthreads();
    }
    int run = (tid == 0) ? 0 : partial[tid - 1];
    for (int i = 0; i < CH; i++) {
        int idx = base + i;
        if (idx < NN) {
            g_ptr[idx] = run;
            g_cur[idx] = run;
            run += g_cnt[idx];
        }
    }
    if (tid == 0) g_ptr[NN] = EE;
}
__global__ void k_scatter(const int* __restrict__ esrc, const int* __restrict__ edst,
                          const int* __restrict__ erel) {
    int e = blockIdx.x * blockDim.x + threadIdx.x;
    if (e < EE) {
        int d = edst[e];
        int p = atomicAdd(&g_cur[d], 1);
        g_ssrc[p] = esrc[e];
        g_srel[p] = erel[e];
    }
}

// ---------------- per-relation: l2norm rows + exp(attention score) tables ----------------
__global__ void k_relnorm(const float* __restrict__ rel_emb,
                          const float* __restrict__ attn_e,
                          const float* __restrict__ attn_r) {
    __shared__ float sh[32];
    int r = blockIdx.x, t = threadIdx.x;
    float v = rel_emb[r * FF + t];
    float s = blockSum(v * v, sh);
    float inv = 1.f / fmaxf(sqrtf(s), 1e-12f);
    float rn = v * inv;
    g_relnorm[r * FF + t] = rn;
    float d0 = blockSum(rn * attn_e[t], sh);
    float d1 = blockSum(rn * attn_e[FF + t], sh);
    float d2 = blockSum(rn * attn_r[t], sh);
    float d3 = blockSum(rn * attn_r[FF + t], sh);
    if (t == 0) {
        g_exps[(0 * LDP + 0) * RR + r] = expf(d0);
        g_exps[(0 * LDP + 1) * RR + r] = expf(d1);
        g_exps[(1 * LDP + 0) * RR + r] = expf(d2);
        g_exps[(1 * LDP + 1) * RR + r] = expf(d3);
    }
}

// ---------------- l2norm proxy rows (stored transposed) ----------------
__global__ void k_proxyn(const float* __restrict__ pe, const float* __restrict__ pr) {
    __shared__ float sh[32];
    int dual = blockIdx.x >> 6, p = blockIdx.x & 63, t = threadIdx.x;
    const float* src = dual ? pr : pe;
    float v = src[p * FDIM + t];
    float s = blockSum(v * v, sh);
    float inv = 1.f / fmaxf(sqrtf(s), 1e-12f);
    g_proxynT[dual][t * PP + p] = v * inv;
}

// ---------------- initial features: tanh(mean of neighbor emb), unrolled x4 ----------------
__global__ void k_init(const float* __restrict__ ent, const float* __restrict__ rel) {
    int warp = threadIdx.x >> 5, lane = threadIdx.x & 31;
    int n = blockIdx.x * 8 + warp;
    if (n >= NN) return;
    int beg = g_ptr[n], end = g_ptr[n + 1];
    float4 ae = {0, 0, 0, 0}, ar = {0, 0, 0, 0};
    int i = beg;
    for (; i + 4 <= end; i += 4) {
        int s[4], r[4];
#pragma unroll
        for (int j = 0; j < 4; j++) { s[j] = g_ssrc[i + j]; r[j] = g_srel[i + j]; }
        float4 a[4], b[4];
#pragma unroll
        for (int j = 0; j < 4; j++) {
            a[j] = *(const float4*)&ent[(size_t)s[j] * FF + lane * 4];
            b[j] = *(const float4*)&rel[(size_t)r[j] * FF + lane * 4];
        }
#pragma unroll
        for (int j = 0; j < 4; j++) {
            ae.x += a[j].x; ae.y += a[j].y; ae.z += a[j].z; ae.w += a[j].w;
            ar.x += b[j].x; ar.y += b[j].y; ar.z += b[j].z; ar.w += b[j].w;
        }
    }
    for (; i < end; i++) {
        int s = g_ssrc[i], r = g_srel[i];
        float4 a = *(const float4*)&ent[(size_t)s * FF + lane * 4];
        float4 b = *(const float4*)&rel[(size_t)r * FF + lane * 4];
        ae.x += a.x; ae.y += a.y; ae.z += a.z; ae.w += a.w;
        ar.x += b.x; ar.y += b.y; ar.z += b.z; ar.w += b.w;
    }
    float inv = 1.f / fmaxf((float)(end - beg), 1.f);
    float* oe = g_oute + (size_t)n * FDIM + lane * 4;
    float* orr = g_outr + (size_t)n * FDIM + lane * 4;
    oe[0] = tanhf(ae.x * inv); oe[1] = tanhf(ae.y * inv);
    oe[2] = tanhf(ae.z * inv); oe[3] = tanhf(ae.w * inv);
    orr[0] = tanhf(ar.x * inv); orr[1] = tanhf(ar.y * inv);
    orr[2] = tanhf(ar.z * inv); orr[3] = tanhf(ar.w * inv);
}

// ---------------- GNN layer: exp-table softmax + Householder agg, unrolled x4 ----------------
__global__ void k_layer(int l) {
    int warp = threadIdx.x >> 5, lane = threadIdx.x & 31;
    int n = blockIdx.x * 8 + warp;
    if (n >= NN) return;
    const float* __restrict__ exe = g_exps + (0 * LDP + l) * RR;
    const float* __restrict__ exr = g_exps + (1 * LDP + l) * RR;
    int beg = g_ptr[n], end = g_ptr[n + 1];

    // sum of unnormalized softmax weights (no max shift needed: |score| <~ 1.5)
    float se = 0.f, sr = 0.f;
    for (int i = beg + lane; i < end; i += 32) {
        int r = g_srel[i];
        se += exe[r];
        sr += exr[r];
    }
    se = warpSum(se); sr = warpSum(sr);
    float ise = (se > 0.f) ? 1.f / se : 0.f;
    float isr = (sr > 0.f) ? 1.f / sr : 0.f;

    float4 acce = {0, 0, 0, 0}, accr = {0, 0, 0, 0};
    int co = l * FF + lane * 4;
    int i = beg;
    for (; i + 4 <= end; i += 4) {
        int s[4], r[4];
#pragma unroll
        for (int j = 0; j < 4; j++) { s[j] = g_ssrc[i + j]; r[j] = g_srel[i + j]; }
        float4 rn[4], fe[4], fr[4];
#pragma unroll
        for (int j = 0; j < 4; j++) {
            rn[j] = *(const float4*)&g_relnorm[r[j] * FF + lane * 4];
            fe[j] = *(const float4*)&g_oute[(size_t)s[j] * FDIM + co];
            fr[j] = *(const float4*)&g_outr[(size_t)s[j] * FDIM + co];
        }
        float de[4], dr[4];
#pragma unroll
        for (int j = 0; j < 4; j++) {
            de[j] = fe[j].x * rn[j].x + fe[j].y * rn[j].y + fe[j].z * rn[j].z + fe[j].w * rn[j].w;
            dr[j] = fr[j].x * rn[j].x + fr[j].y * rn[j].y + fr[j].z * rn[j].z + fr[j].w * rn[j].w;
        }
#pragma unroll
        for (int o = 16; o; o >>= 1) {
#pragma unroll
            for (int j = 0; j < 4; j++) {
                de[j] += __shfl_xor_sync(0xffffffffu, de[j], o);
                dr[j] += __shfl_xor_sync(0xffffffffu, dr[j], o);
            }
        }
#pragma unroll
        for (int j = 0; j < 4; j++) {
            float we = exe[r[j]], wr = exr[r[j]];
            float ce = -2.f * de[j], cr = -2.f * dr[j];
            acce.x += we * (fe[j].x + ce * rn[j].x); acce.y += we * (fe[j].y + ce * rn[j].y);
            acce.z += we * (fe[j].z + ce * rn[j].z); acce.w += we * (fe[j].w + ce * rn[j].w);
            accr.x += wr * (fr[j].x + cr * rn[j].x); accr.y += wr * (fr[j].y + cr * rn[j].y);
            accr.z += wr * (fr[j].z + cr * rn[j].z); accr.w += wr * (fr[j].w + cr * rn[j].w);
        }
    }
    for (; i < end; i++) {
        int s = g_ssrc[i], r = g_srel[i];
        float we = exe[r], wr = exr[r];
        float4 rn = *(const float4*)&g_relnorm[r * FF + lane * 4];
        float4 fe = *(const float4*)&g_oute[(size_t)s * FDIM + co];
        float4 fr = *(const float4*)&g_outr[(size_t)s * FDIM + co];
        float de = fe.x * rn.x + fe.y * rn.y + fe.z * rn.z + fe.w * rn.w;
        float dr = fr.x * rn.x + fr.y * rn.y + fr.z * rn.z + fr.w * rn.w;
#pragma unroll
        for (int o = 16; o; o >>= 1) {
            de += __shfl_xor_sync(0xffffffffu, de, o);
            dr += __shfl_xor_sync(0xffffffffu, dr, o);
        }
        float ce = -2.f * de, cr = -2.f * dr;
        acce.x += we * (fe.x + ce * rn.x); acce.y += we * (fe.y + ce * rn.y);
        acce.z += we * (fe.z + ce * rn.z); acce.w += we * (fe.w + ce * rn.w);
        accr.x += wr * (fr.x + cr * rn.x); accr.y += wr * (fr.y + cr * rn.y);
        accr.z += wr * (fr.z + cr * rn.z); accr.w += wr * (fr.w + cr * rn.w);
    }
    float* oe = g_oute + (size_t)n * FDIM + (l + 1) * FF + lane * 4;
    float* orr = g_outr + (size_t)n * FDIM + (l + 1) * FF + lane * 4;
    oe[0] = tanhf(acce.x * ise); oe[1] = tanhf(acce.y * ise);
    oe[2] = tanhf(acce.z * ise); oe[3] = tanhf(acce.w * ise);
    orr[0] = tanhf(accr.x * isr); orr[1] = tanhf(accr.y * isr);
    orr[2] = tanhf(accr.z * isr); orr[3] = tanhf(accr.w * isr);
}

// ---------------- row inverse norms ----------------
__global__ void k_invnorm() {
    int w = blockIdx.x * 8 + (threadIdx.x >> 5);
    int lane = threadIdx.x & 31;
    if (w >= 2 * NN) return;
    int dual = w / NN, row = w % NN;
    const float* x = (dual ? g_outr : g_oute) + (size_t)row * FDIM;
    float s = 0.f;
#pragma unroll
    for (int k = 0; k < 3; k++) {
        float4 v = *(const float4*)&x[k * 128 + lane * 4];
        s += v.x * v.x + v.y * v.y + v.z * v.z + v.w * v.w;
    }
    s = warpSum(s);
    if (lane == 0) g_invn[dual][row] = 1.f / fmaxf(sqrtf(s), 1e-12f);
}

// ================= tensor-core (tf32 mma) GEMMs, duals merged on blockIdx.z =================
// GEMM1: logits = invn * (X @ proxynT), fused row softmax -> g_attw
__global__ __launch_bounds__(256) void k_gemm1t() {
    __shared__ union {
        struct { unsigned As[128][36]; unsigned Bs[32][72]; } s;
        float Ls[128][66];
    } u;
    int dual = blockIdx.z;
    int mb = blockIdx.x * 128;
    const float* X = dual ? g_outr : g_oute;
    const float* BT = g_proxynT[dual];
    float* attw = g_attw + (size_t)dual * NN * PP;
    int tid = threadIdx.x, lane = tid & 31, wid = tid >> 5;
    int g = lane >> 2, t4 = lane & 3;
    int warpM = wid * 16;
    float acc[8][4] = {};
    for (int kc = 0; kc < FDIM; kc += 32) {
#pragma unroll
        for (int i = 0; i < 4; i++) {
            int id = tid + i * 256;
            int row = id >> 3, kq = (id & 7) * 4;
            float4 v = {0, 0, 0, 0};
            if (mb + row < NN) v = *(const float4*)&X[(size_t)(mb + row) * FDIM + kc + kq];
            u.s.As[row][kq] = f2tf(v.x); u.s.As[row][kq + 1] = f2tf(v.y);
            u.s.As[row][kq + 2] = f2tf(v.z); u.s.As[row][kq + 3] = f2tf(v.w);
        }
#pragma unroll
        for (int i = 0; i < 2; i++) {
            int id = tid + i * 256;
            int k = id >> 4, cq = (id & 15) * 4;
            float4 v = *(const float4*)&BT[(size_t)(kc + k) * PP + cq];
            u.s.Bs[k][cq] = f2tf(v.x); u.s.Bs[k][cq + 1] = f2tf(v.y);
            u.s.Bs[k][cq + 2] = f2tf(v.z); u.s.Bs[k][cq + 3] = f2tf(v.w);
        }
        __syncthreads();
#pragma unroll
        for (int ks = 0; ks < 4; ks++) {
            int k0 = ks * 8;
            unsigned a[4], b[8][2];
            a[0] = u.s.As[warpM + g][k0 + t4];
            a[1] = u.s.As[warpM + g + 8][k0 + t4];
            a[2] = u.s.As[warpM + g][k0 + t4 + 4];
            a[3] = u.s.As[warpM + g + 8][k0 + t4 + 4];
#pragma unroll
            for (int nt = 0; nt < 8; nt++) {
                b[nt][0] = u.s.Bs[k0 + t4][nt * 8 + g];
                b[nt][1] = u.s.Bs[k0 + t4 + 4][nt * 8 + g];
            }
#pragma unroll
            for (int nt = 0; nt < 8; nt++) mma_tf32(acc[nt], a, b[nt]);
        }
        __syncthreads();
    }
#pragma unroll
    for (int nt = 0; nt < 8; nt++) {
        int r0 = warpM + g, r1 = warpM + g + 8, c0 = nt * 8 + t4 * 2;
        float i0 = (mb + r0 < NN) ? g_invn[dual][mb + r0] : 1.f;
        float i1 = (mb + r1 < NN) ? g_invn[dual][mb + r1] : 1.f;
        u.Ls[r0][c0] = acc[nt][0] * i0; u.Ls[r0][c0 + 1] = acc[nt][1] * i0;
        u.Ls[r1][c0] = acc[nt][2] * i1; u.Ls[r1][c0 + 1] = acc[nt][3] * i1;
    }
    __syncthreads();
    if (tid < 128) {
        int gn = mb + tid;
        if (gn < NN) {
            float m = -3e38f;
            for (int c = 0; c < PP; c++) m = fmaxf(m, u.Ls[tid][c]);
            float s = 0.f;
            for (int c = 0; c < PP; c++) s += expf(u.Ls[tid][c] - m);
            float is = 1.f / s;
            for (int c = 0; c < PP; c++)
                attw[(size_t)gn * PP + c] = expf(u.Ls[tid][c] - m) * is;
        }
    }
}

// GEMM2: pf = X - attw @ proxy
__global__ __launch_bounds__(256) void k_gemm2t(const float* __restrict__ proxy_e,
                                                const float* __restrict__ proxy_r) {
    __shared__ unsigned As[128][36];
    __shared__ unsigned Bs[32][136];
    int dual = blockIdx.z;
    int mb = blockIdx.x * 128, nb = blockIdx.y * 128;
    const float* X = dual ? g_outr : g_oute;
    const float* proxy = dual ? proxy_r : proxy_e;
    const float* attw = g_attw + (size_t)dual * NN * PP;
    float* pf = g_pf + (size_t)dual * NN * FDIM;
    int tid = threadIdx.x, lane = tid & 31, wid = tid >> 5;
    int g = lane >> 2, t4 = lane & 3;
    int warpM = (wid & 3) * 32, warpN = (wid >> 2) * 64;
    float acc[2][8][4] = {};
    for (int kc = 0; kc < PP; kc += 32) {
#pragma unroll
        for (int i = 0; i < 4; i++) {
            int id = tid + i * 256;
            int row = id >> 3, kq = (id & 7) * 4;
            float4 v = {0, 0, 0, 0};
            if (mb + row < NN) v = *(const float4*)&attw[(size_t)(mb + row) * PP + kc + kq];
            As[row][kq] = f2tf(v.x); As[row][kq + 1] = f2tf(v.y);
            As[row][kq + 2] = f2tf(v.z); As[row][kq + 3] = f2tf(v.w);
        }
#pragma unroll
        for (int i = 0; i < 4; i++) {
            int id = tid + i * 256;
            int k = id >> 5, cq = (id & 31) * 4;
            float4 v = *(const float4*)&proxy[(size_t)(kc + k) * FDIM + nb + cq];
            Bs[k][cq] = f2tf(v.x); Bs[k][cq + 1] = f2tf(v.y);
            Bs[k][cq + 2] = f2tf(v.z); Bs[k][cq + 3] = f2tf(v.w);
        }
        __syncthreads();
#pragma unroll
        for (int ks = 0; ks < 4; ks++) {
            int k0 = ks * 8;
            unsigned a[2][4], b[8][2];
#pragma unroll
            for (int mt = 0; mt < 2; mt++) {
                int r = warpM + mt * 16;
                a[mt][0] = As[r + g][k0 + t4];
                a[mt][1] = As[r + g + 8][k0 + t4];
                a[mt][2] = As[r + g][k0 + t4 + 4];
                a[mt][3] = As[r + g + 8][k0 + t4 + 4];
            }
#pragma unroll
            for (int nt = 0; nt < 8; nt++) {
                b[nt][0] = Bs[k0 + t4][warpN + nt * 8 + g];
                b[nt][1] = Bs[k0 + t4 + 4][warpN + nt * 8 + g];
            }
#pragma unroll
            for (int mt = 0; mt < 2; mt++)
#pragma unroll
                for (int nt = 0; nt < 8; nt++) mma_tf32(acc[mt][nt], a[mt], b[nt]);
        }
        __syncthreads();
    }
#pragma unroll
    for (int mt = 0; mt < 2; mt++) {
#pragma unroll
        for (int nt = 0; nt < 8; nt++) {
            int col = nb + warpN + nt * 8 + t4 * 2;
            int r0 = mb + warpM + mt * 16 + g, r1 = r0 + 8;
            if (r0 < NN) {
                float2 x = *(const float2*)&X[(size_t)r0 * FDIM + col];
                float2 o = {x.x - acc[mt][nt][0], x.y - acc[mt][nt][1]};
                *(float2*)&pf[(size_t)r0 * FDIM + col] = o;
            }
            if (r1 < NN) {
                float2 x = *(const float2*)&X[(size_t)r1 * FDIM + col];
                float2 o = {x.x - acc[mt][nt][2], x.y - acc[mt][nt][3]};
                *(float2*)&pf[(size_t)r1 * FDIM + col] = o;
            }
        }
    }
}

// GEMM3: gate = sigmoid(pf@G + b); out = gate*X + (1-gate)*pf
__global__ __launch_bounds__(256) void k_gemm3t(const float* __restrict__ G_e,
                                                const float* __restrict__ G_r,
                                                const float* __restrict__ bias_e,
                                                const float* __restrict__ bias_r,
                                                float* __restrict__ out) {
    __shared__ unsigned As[128][36];
    __shared__ unsigned Bs[32][136];
    int dual = blockIdx.z;
    int mb = blockIdx.x * 128, nb = blockIdx.y * 128;
    const float* X = dual ? g_outr : g_oute;
    const float* G = dual ? G_r : G_e;
    const float* bias = dual ? bias_r : bias_e;
    const float* pf = g_pf + (size_t)dual * NN * FDIM;
    int tid = threadIdx.x, lane = tid & 31, wid = tid >> 5;
    int g = lane >> 2, t4 = lane & 3;
    int warpM = (wid & 3) * 32, warpN = (wid >> 2) * 64;
    float acc[2][8][4] = {};
    for (int kc = 0; kc < FDIM; kc += 32) {
#pragma unroll
        for (int i = 0; i < 4; i++) {
            int id = tid + i * 256;
            int row = id >> 3, kq = (id & 7) * 4;
            float4 v = {0, 0, 0, 0};
            if (mb + row < NN) v = *(const float4*)&pf[(size_t)(mb + row) * FDIM + kc + kq];
            As[row][kq] = f2tf(v.x); As[row][kq + 1] = f2tf(v.y);
            As[row][kq + 2] = f2tf(v.z); As[row][kq + 3] = f2tf(v.w);
        }
#pragma unroll
        for (int i = 0; i < 4; i++) {
            int id = tid + i * 256;
            int k = id >> 5, cq = (id & 31) * 4;
            float4 v = *(const float4*)&G[(size_t)(kc + k) * FDIM + nb + cq];
            Bs[k][cq] = f2tf(v.x); Bs[k][cq + 1] = f2tf(v.y);
            Bs[k][cq + 2] = f2tf(v.z); Bs[k][cq + 3] = f2tf(v.w);
        }
        __syncthreads();
#pragma unroll
        for (int ks = 0; ks < 4; ks++) {
            int k0 = ks * 8;
            unsigned a[2][4], b[8][2];
#pragma unroll
            for (int mt = 0; mt < 2; mt++) {
                int r = warpM + mt * 16;
                a[mt][0] = As[r + g][k0 + t4];
                a[mt][1] = As[r + g + 8][k0 + t4];
                a[mt][2] = As[r + g][k0 + t4 + 4];
                a[mt][3] = As[r + g + 8][k0 + t4 + 4];
            }
#pragma unroll
            for (int nt = 0; nt < 8; nt++) {
                b[nt][0] = Bs[k0 + t4][warpN + nt * 8 + g];
                b[nt][1] = Bs[k0 + t4 + 4][warpN + nt * 8 + g];
            }
#pragma unroll
            for (int mt = 0; mt < 2; mt++)
#pragma unroll
                for (int nt = 0; nt < 8; nt++) mma_tf32(acc[mt][nt], a[mt], b[nt]);
        }
        __syncthreads();
    }
#pragma unroll
    for (int mt = 0; mt < 2; mt++) {
#pragma unroll
        for (int nt = 0; nt < 8; nt++) {
            int col = nb + warpN + nt * 8 + t4 * 2;
            float b0 = bias[col], b1 = bias[col + 1];
            int r0 = mb + warpM + mt * 16 + g, r1 = r0 + 8;
            if (r0 < NN) {
                float g0 = 1.f / (1.f + expf(-(acc[mt][nt][0] + b0)));
                float g1 = 1.f / (1.f + expf(-(acc[mt][nt][1] + b1)));
                float2 x = *(const float2*)&X[(size_t)r0 * FDIM + col];
                float2 p = *(const float2*)&pf[(size_t)r0 * FDIM + col];
                float2 o = {g0 * x.x + (1.f - g0) * p.x, g1 * x.y + (1.f - g1) * p.y};
                *(float2*)&out[(size_t)r0 * (2 * FDIM) + dual * FDIM + col] = o;
            }
            if (r1 < NN) {
                float g0 = 1.f / (1.f + expf(-(acc[mt][nt][2] + b0)));
                float g1 = 1.f / (1.f + expf(-(acc[mt][nt][3] + b1)));
                float2 x = *(const float2*)&X[(size_t)r1 * FDIM + col];
                float2 p = *(const float2*)&pf[(size_t)r1 * FDIM + col];
                float2 o = {g0 * x.x + (1.f - g0) * p.x, g1 * x.y + (1.f - g1) * p.y};
                *(float2*)&out[(size_t)r1 * (2 * FDIM) + dual * FDIM + col] = o;
            }
        }
    }
}

// ---------------- launch ----------------
extern "C" void kernel_launch(void* const* d_in, const int* in_sizes, int n_in,
                              void* d_out, int out_size) {
    const float* ent     = (const float*)d_in[0];
    const float* rel     = (const float*)d_in[1];
    const int*   esrc    = (const int*)d_in[2];
    const int*   edst    = (const int*)d_in[3];
    const int*   erel    = (const int*)d_in[4];
    const float* attn_e  = (const float*)d_in[5];
    const float* gate_e  = (const float*)d_in[6];
    const float* proxy_e = (const float*)d_in[7];
    const float* bias_e  = (const float*)d_in[8];
    const float* attn_r  = (const float*)d_in[9];
    const float* gate_r  = (const float*)d_in[10];
    const float* proxy_r = (const float*)d_in[11];
    const float* bias_r  = (const float*)d_in[12];
    float* out = (float*)d_out;

    k_zero<<<196, 256>>>();
    k_hist<<<3125, 256>>>(edst);
    k_scan<<<1, 1024>>>();
    k_scatter<<<3125, 256>>>(esrc, edst, erel);
    k_relnorm<<<RR, FF>>>(rel, attn_e, attn_r);
    k_proxyn<<<128, FDIM>>>(proxy_e, proxy_r);
    k_init<<<6250, 256>>>(ent, rel);
    k_layer<<<6250, 256>>>(0);
    k_layer<<<6250, 256>>>(1);
    k_invnorm<<<12500, 256>>>();
    k_gemm1t<<<dim3(391, 1, 2), 256>>>();
    k_gemm2t<<<dim3(391, 3, 2), 256>>>(proxy_e, proxy_r);
    k_gemm3t<<<dim3(391, 3, 2), 256>>>(gate_e, gate_r, bias_e, bias_r, out);
}

// round 4
// speedup vs baseline: 1.6927x; 1.0668x over previous
#include <cuda_runtime.h>
#include <math.h>

#define NN 50000
#define EE 800000
#define RR 2000
#define FF 128
#define LDP 2
#define FDIM 384
#define PP 64

// ---------------- scratch (device globals; no allocation allowed) ----------------
__device__ int   g_cnt[NN];
__device__ int   g_ptr[NN + 1];
__device__ int   g_cur[NN];
__device__ int   g_ssrc[EE];
__device__ int   g_srel[EE];
__device__ float g_relnorm[RR * FF];
__device__ float g_exps[2 * LDP * RR];            // exp(score) [dual][layer][r]
__device__ float g_oute[(size_t)NN * FDIM];
__device__ float g_outr[(size_t)NN * FDIM];
__device__ float g_proxynT[2][FDIM * PP];         // l2-normed proxy, transposed [k][p]
__device__ float g_invn[2][NN];
__device__ float g_attw[(size_t)2 * NN * PP];
__device__ float g_pf[(size_t)2 * NN * FDIM];

// ---------------- helpers ----------------
__device__ __forceinline__ float warpSum(float v) {
#pragma unroll
    for (int o = 16; o; o >>= 1) v += __shfl_xor_sync(0xffffffffu, v, o);
    return v;
}
__device__ __forceinline__ float blockSum(float v, float* sh) {
    int lane = threadIdx.x & 31, w = threadIdx.x >> 5;
    v = warpSum(v);
    if (lane == 0) sh[w] = v;
    __syncthreads();
    if (threadIdx.x == 0) {
        int nw = (blockDim.x + 31) >> 5;
        float r = 0.f;
        for (int i = 0; i < nw; i++) r += sh[i];
        sh[0] = r;
    }
    __syncthreads();
    float r = sh[0];
    __syncthreads();
    return r;
}
__device__ __forceinline__ void mma_tf32(float* c, const unsigned* a, const unsigned* b) {
    asm volatile(
        "mma.sync.aligned.m16n8k8.row.col.f32.tf32.tf32.f32 "
        "{%0,%1,%2,%3}, {%4,%5,%6,%7}, {%8,%9}, {%0,%1,%2,%3};"
        : "+f"(c[0]), "+f"(c[1]), "+f"(c[2]), "+f"(c[3])
        : "r"(a[0]), "r"(a[1]), "r"(a[2]), "r"(a[3]), "r"(b[0]), "r"(b[1]));
}
__device__ __forceinline__ unsigned smemA(const void* p) {
    return (unsigned)__cvta_generic_to_shared(p);
}
#define CP16(dst, src) asm volatile("cp.async.cg.shared.global [%0], [%1], 16;" ::"r"(dst), "l"(src))
#define CPCOMMIT() asm volatile("cp.async.commit_group;")
#define CPWAIT1() asm volatile("cp.async.wait_group 1;")
#define CPWAIT0() asm volatile("cp.async.wait_group 0;")

// ---------------- CSR build ----------------
__global__ void k_zero() {
    int i = blockIdx.x * blockDim.x + threadIdx.x;
    if (i < NN) g_cnt[i] = 0;
}
__global__ void k_hist(const int* __restrict__ edst) {
    int e = blockIdx.x * blockDim.x + threadIdx.x;
    if (e < EE) atomicAdd(&g_cnt[edst[e]], 1);
}
__global__ void k_scan() {
    __shared__ int partial[1024];
    int tid = threadIdx.x;
    const int CH = 49;
    int base = tid * CH;
    int s = 0;
    for (int i = 0; i < CH; i++) {
        int idx = base + i;
        if (idx < NN) s += g_cnt[idx];
    }
    partial[tid] = s;
    __syncthreads();
    for (int off = 1; off < 1024; off <<= 1) {
        int v = (tid >= off) ? partial[tid - off] : 0;
        __syncthreads();
        partial[tid] += v;
        __syncthreads();
    }
    int run = (tid == 0) ? 0 : partial[tid - 1];
    for (int i = 0; i < CH; i++) {
        int idx = base + i;
        if (idx < NN) {
            g_ptr[idx] = run;
            g_cur[idx] = run;
            run += g_cnt[idx];
        }
    }
    if (tid == 0) g_ptr[NN] = EE;
}
__global__ void k_scatter(const int* __restrict__ esrc, const int* __restrict__ edst,
                          const int* __restrict__ erel) {
    int e = blockIdx.x * blockDim.x + threadIdx.x;
    if (e < EE) {
        int d = edst[e];
        int p = atomicAdd(&g_cur[d], 1);
        g_ssrc[p] = esrc[e];
        g_srel[p] = erel[e];
    }
}

// ---------------- per-relation: l2norm rows + exp(score) tables ----------------
__global__ void k_relnorm(const float* __restrict__ rel_emb,
                          const float* __restrict__ attn_e,
                          const float* __restrict__ attn_r) {
    __shared__ float sh[32];
    int r = blockIdx.x, t = threadIdx.x;
    float v = rel_emb[r * FF + t];
    float s = blockSum(v * v, sh);
    float inv = 1.f / fmaxf(sqrtf(s), 1e-12f);
    float rn = v * inv;
    g_relnorm[r * FF + t] = rn;
    float d0 = blockSum(rn * attn_e[t], sh);
    float d1 = blockSum(rn * attn_e[FF + t], sh);
    float d2 = blockSum(rn * attn_r[t], sh);
    float d3 = blockSum(rn * attn_r[FF + t], sh);
    if (t == 0) {
        g_exps[(0 * LDP + 0) * RR + r] = expf(d0);
        g_exps[(0 * LDP + 1) * RR + r] = expf(d1);
        g_exps[(1 * LDP + 0) * RR + r] = expf(d2);
        g_exps[(1 * LDP + 1) * RR + r] = expf(d3);
    }
}

// ---------------- l2norm proxy rows (transposed) ----------------
__global__ void k_proxyn(const float* __restrict__ pe, const float* __restrict__ pr) {
    __shared__ float sh[32];
    int dual = blockIdx.x >> 6, p = blockIdx.x & 63, t = threadIdx.x;
    const float* src = dual ? pr : pe;
    float v = src[p * FDIM + t];
    float s = blockSum(v * v, sh);
    float inv = 1.f / fmaxf(sqrtf(s), 1e-12f);
    g_proxynT[dual][t * PP + p] = v * inv;
}

// ---------------- initial features ----------------
__global__ void k_init(const float* __restrict__ ent, const float* __restrict__ rel) {
    int warp = threadIdx.x >> 5, lane = threadIdx.x & 31;
    int n = blockIdx.x * 8 + warp;
    if (n >= NN) return;
    int beg = g_ptr[n], end = g_ptr[n + 1];
    float4 ae = {0, 0, 0, 0}, ar = {0, 0, 0, 0};
    int i = beg;
    for (; i + 4 <= end; i += 4) {
        int s[4], r[4];
#pragma unroll
        for (int j = 0; j < 4; j++) { s[j] = g_ssrc[i + j]; r[j] = g_srel[i + j]; }
        float4 a[4], b[4];
#pragma unroll
        for (int j = 0; j < 4; j++) {
            a[j] = *(const float4*)&ent[(size_t)s[j] * FF + lane * 4];
            b[j] = *(const float4*)&rel[(size_t)r[j] * FF + lane * 4];
        }
#pragma unroll
        for (int j = 0; j < 4; j++) {
            ae.x += a[j].x; ae.y += a[j].y; ae.z += a[j].z; ae.w += a[j].w;
            ar.x += b[j].x; ar.y += b[j].y; ar.z += b[j].z; ar.w += b[j].w;
        }
    }
    for (; i < end; i++) {
        int s = g_ssrc[i], r = g_srel[i];
        float4 a = *(const float4*)&ent[(size_t)s * FF + lane * 4];
        float4 b = *(const float4*)&rel[(size_t)r * FF + lane * 4];
        ae.x += a.x; ae.y += a.y; ae.z += a.z; ae.w += a.w;
        ar.x += b.x; ar.y += b.y; ar.z += b.z; ar.w += b.w;
    }
    float inv = 1.f / fmaxf((float)(end - beg), 1.f);
    float* oe = g_oute + (size_t)n * FDIM + lane * 4;
    float* orr = g_outr + (size_t)n * FDIM + lane * 4;
    oe[0] = tanhf(ae.x * inv); oe[1] = tanhf(ae.y * inv);
    oe[2] = tanhf(ae.z * inv); oe[3] = tanhf(ae.w * inv);
    orr[0] = tanhf(ar.x * inv); orr[1] = tanhf(ar.y * inv);
    orr[2] = tanhf(ar.z * inv); orr[3] = tanhf(ar.w * inv);
}

// ---------------- GNN layer ----------------
__global__ void k_layer(int l) {
    int warp = threadIdx.x >> 5, lane = threadIdx.x & 31;
    int n = blockIdx.x * 8 + warp;
    if (n >= NN) return;
    const float* __restrict__ exe = g_exps + (0 * LDP + l) * RR;
    const float* __restrict__ exr = g_exps + (1 * LDP + l) * RR;
    int beg = g_ptr[n], end = g_ptr[n + 1];

    float se = 0.f, sr = 0.f;
    for (int i = beg + lane; i < end; i += 32) {
        int r = g_srel[i];
        se += exe[r];
        sr += exr[r];
    }
    se = warpSum(se); sr = warpSum(sr);
    float ise = (se > 0.f) ? 1.f / se : 0.f;
    float isr = (sr > 0.f) ? 1.f / sr : 0.f;

    float4 acce = {0, 0, 0, 0}, accr = {0, 0, 0, 0};
    int co = l * FF + lane * 4;
    int i = beg;
    for (; i + 4 <= end; i += 4) {
        int s[4], r[4];
#pragma unroll
        for (int j = 0; j < 4; j++) { s[j] = g_ssrc[i + j]; r[j] = g_srel[i + j]; }
        float4 rn[4], fe[4], fr[4];
#pragma unroll
        for (int j = 0; j < 4; j++) {
            rn[j] = *(const float4*)&g_relnorm[r[j] * FF + lane * 4];
            fe[j] = *(const float4*)&g_oute[(size_t)s[j] * FDIM + co];
            fr[j] = *(const float4*)&g_outr[(size_t)s[j] * FDIM + co];
        }
        float de[4], dr[4];
#pragma unroll
        for (int j = 0; j < 4; j++) {
            de[j] = fe[j].x * rn[j].x + fe[j].y * rn[j].y + fe[j].z * rn[j].z + fe[j].w * rn[j].w;
            dr[j] = fr[j].x * rn[j].x + fr[j].y * rn[j].y + fr[j].z * rn[j].z + fr[j].w * rn[j].w;
        }
#pragma unroll
        for (int o = 16; o; o >>= 1) {
#pragma unroll
            for (int j = 0; j < 4; j++) {
                de[j] += __shfl_xor_sync(0xffffffffu, de[j], o);
                dr[j] += __shfl_xor_sync(0xffffffffu, dr[j], o);
            }
        }
#pragma unroll
        for (int j = 0; j < 4; j++) {
            float we = exe[r[j]], wr = exr[r[j]];
            float ce = -2.f * de[j], cr = -2.f * dr[j];
            acce.x += we * (fe[j].x + ce * rn[j].x); acce.y += we * (fe[j].y + ce * rn[j].y);
            acce.z += we * (fe[j].z + ce * rn[j].z); acce.w += we * (fe[j].w + ce * rn[j].w);
            accr.x += wr * (fr[j].x + cr * rn[j].x); accr.y += wr * (fr[j].y + cr * rn[j].y);
            accr.z += wr * (fr[j].z + cr * rn[j].z); accr.w += wr * (fr[j].w + cr * rn[j].w);
        }
    }
    for (; i < end; i++) {
        int s = g_ssrc[i], r = g_srel[i];
        float we = exe[r], wr = exr[r];
        float4 rn = *(const float4*)&g_relnorm[r * FF + lane * 4];
        float4 fe = *(const float4*)&g_oute[(size_t)s * FDIM + co];
        float4 fr = *(const float4*)&g_outr[(size_t)s * FDIM + co];
        float de = fe.x * rn.x + fe.y * rn.y + fe.z * rn.z + fe.w * rn.w;
        float dr = fr.x * rn.x + fr.y * rn.y + fr.z * rn.z + fr.w * rn.w;
#pragma unroll
        for (int o = 16; o; o >>= 1) {
            de += __shfl_xor_sync(0xffffffffu, de, o);
            dr += __shfl_xor_sync(0xffffffffu, dr, o);
        }
        float ce = -2.f * de, cr = -2.f * dr;
        acce.x += we * (fe.x + ce * rn.x); acce.y += we * (fe.y + ce * rn.y);
        acce.z += we * (fe.z + ce * rn.z); acce.w += we * (fe.w + ce * rn.w);
        accr.x += wr * (fr.x + cr * rn.x); accr.y += wr * (fr.y + cr * rn.y);
        accr.z += wr * (fr.z + cr * rn.z); accr.w += wr * (fr.w + cr * rn.w);
    }
    float* oe = g_oute + (size_t)n * FDIM + (l + 1) * FF + lane * 4;
    float* orr = g_outr + (size_t)n * FDIM + (l + 1) * FF + lane * 4;
    oe[0] = tanhf(acce.x * ise); oe[1] = tanhf(acce.y * ise);
    oe[2] = tanhf(acce.z * ise); oe[3] = tanhf(acce.w * ise);
    orr[0] = tanhf(accr.x * isr); orr[1] = tanhf(accr.y * isr);
    orr[2] = tanhf(accr.z * isr); orr[3] = tanhf(accr.w * isr);
}

// ---------------- row inverse norms ----------------
__global__ void k_invnorm() {
    int w = blockIdx.x * 8 + (threadIdx.x >> 5);
    int lane = threadIdx.x & 31;
    if (w >= 2 * NN) return;
    int dual = w / NN, row = w % NN;
    const float* x = (dual ? g_outr : g_oute) + (size_t)row * FDIM;
    float s = 0.f;
#pragma unroll
    for (int k = 0; k < 3; k++) {
        float4 v = *(const float4*)&x[k * 128 + lane * 4];
        s += v.x * v.x + v.y * v.y + v.z * v.z + v.w * v.w;
    }
    s = warpSum(s);
    if (lane == 0) g_invn[dual][row] = 1.f / fmaxf(sqrtf(s), 1e-12f);
}

// ================= tf32 mma GEMMs with cp.async double buffering =================
// fp32 bits fed directly to tf32 mma (HW truncation) — no cvt on the load path.

// GEMM1: logits = invn*(X @ proxynT), fused row softmax -> attw. BM=128, BN=64, BK=32, K=384.
__global__ __launch_bounds__(256) void k_gemm1t() {
    __shared__ union {
        struct { unsigned As[2][128][36]; unsigned Bs[2][32][72]; } s;
        float Ls[128][66];
    } u;
    int dual = blockIdx.z;
    int mb = blockIdx.x * 128;
    const float* X = dual ? g_outr : g_oute;
    const float* BT = g_proxynT[dual];
    float* attw = g_attw + (size_t)dual * NN * PP;
    int tid = threadIdx.x, lane = tid & 31, wid = tid >> 5;
    int g = lane >> 2, t4 = lane & 3;
    int warpM = wid * 16;

    // per-thread load coords
    int arow = tid >> 3, akq = (tid & 7) * 4;            // + i*32 rows (4 iters)
    int bk = tid >> 4, bcq = (tid & 15) * 4;             // + i*16 k (2 iters)

    auto loadTiles = [&](int buf, int kc) {
#pragma unroll
        for (int i = 0; i < 4; i++) {
            int row = arow + i * 32;
            int gr = min(mb + row, NN - 1);
            CP16(smemA(&u.s.As[buf][row][akq]), &X[(size_t)gr * FDIM + kc + akq]);
        }
#pragma unroll
        for (int i = 0; i < 2; i++) {
            int k = bk + i * 16;
            CP16(smemA(&u.s.Bs[buf][k][bcq]), &BT[(size_t)(kc + k) * PP + bcq]);
        }
        CPCOMMIT();
    };

    float acc[8][4] = {};
    loadTiles(0, 0);
    const int NT = FDIM / 32;  // 12
    for (int t = 0; t < NT; t++) {
        int buf = t & 1;
        if (t + 1 < NT) { loadTiles(buf ^ 1, (t + 1) * 32); CPWAIT1(); }
        else CPWAIT0();
        __syncthreads();
#pragma unroll
        for (int ks = 0; ks < 4; ks++) {
            int k0 = ks * 8;
            unsigned a[4], b[8][2];
            a[0] = u.s.As[buf][warpM + g][k0 + t4];
            a[1] = u.s.As[buf][warpM + g + 8][k0 + t4];
            a[2] = u.s.As[buf][warpM + g][k0 + t4 + 4];
            a[3] = u.s.As[buf][warpM + g + 8][k0 + t4 + 4];
#pragma unroll
            for (int nt = 0; nt < 8; nt++) {
                b[nt][0] = u.s.Bs[buf][k0 + t4][nt * 8 + g];
                b[nt][1] = u.s.Bs[buf][k0 + t4 + 4][nt * 8 + g];
            }
#pragma unroll
            for (int nt = 0; nt < 8; nt++) mma_tf32(acc[nt], a, b[nt]);
        }
        __syncthreads();
    }
#pragma unroll
    for (int nt = 0; nt < 8; nt++) {
        int r0 = warpM + g, r1 = warpM + g + 8, c0 = nt * 8 + t4 * 2;
        float i0 = (mb + r0 < NN) ? g_invn[dual][mb + r0] : 1.f;
        float i1 = (mb + r1 < NN) ? g_invn[dual][mb + r1] : 1.f;
        u.Ls[r0][c0] = acc[nt][0] * i0; u.Ls[r0][c0 + 1] = acc[nt][1] * i0;
        u.Ls[r1][c0] = acc[nt][2] * i1; u.Ls[r1][c0 + 1] = acc[nt][3] * i1;
    }
    __syncthreads();
    if (tid < 128) {
        int gn = mb + tid;
        if (gn < NN) {
            float m = -3e38f;
            for (int c = 0; c < PP; c++) m = fmaxf(m, u.Ls[tid][c]);
            float s = 0.f;
            for (int c = 0; c < PP; c++) s += expf(u.Ls[tid][c] - m);
            float is = 1.f / s;
            for (int c = 0; c < PP; c++)
                attw[(size_t)gn * PP + c] = expf(u.Ls[tid][c] - m) * is;
        }
    }
}

// GEMM2: pf = X - attw @ proxy. BM=128, BN=128, BK=32, K=64.
__global__ __launch_bounds__(256) void k_gemm2t(const float* __restrict__ proxy_e,
                                                const float* __restrict__ proxy_r) {
    __shared__ unsigned As[2][128][36];
    __shared__ unsigned Bs[2][32][136];
    int dual = blockIdx.z;
    int mb = blockIdx.x * 128, nb = blockIdx.y * 128;
    const float* X = dual ? g_outr : g_oute;
    const float* proxy = dual ? proxy_r : proxy_e;
    const float* attw = g_attw + (size_t)dual * NN * PP;
    float* pf = g_pf + (size_t)dual * NN * FDIM;
    int tid = threadIdx.x, lane = tid & 31, wid = tid >> 5;
    int g = lane >> 2, t4 = lane & 3;
    int warpM = (wid & 3) * 32, warpN = (wid >> 2) * 64;

    int arow = tid >> 3, akq = (tid & 7) * 4;
    int bk = tid >> 5, bcq = (tid & 31) * 4;

    auto loadTiles = [&](int buf, int kc) {
#pragma unroll
        for (int i = 0; i < 4; i++) {
            int row = arow + i * 32;
            int gr = min(mb + row, NN - 1);
            CP16(smemA(&As[buf][row][akq]), &attw[(size_t)gr * PP + kc + akq]);
        }
#pragma unroll
        for (int i = 0; i < 4; i++) {
            int k = bk + i * 8;
            CP16(smemA(&Bs[buf][k][bcq]), &proxy[(size_t)(kc + k) * FDIM + nb + bcq]);
        }
        CPCOMMIT();
    };

    float acc[2][8][4] = {};
    loadTiles(0, 0);
    const int NT = PP / 32;  // 2
    for (int t = 0; t < NT; t++) {
        int buf = t & 1;
        if (t + 1 < NT) { loadTiles(buf ^ 1, (t + 1) * 32); CPWAIT1(); }
        else CPWAIT0();
        __syncthreads();
#pragma unroll
        for (int ks = 0; ks < 4; ks++) {
            int k0 = ks * 8;
            unsigned a[2][4], b[8][2];
#pragma unroll
            for (int mt = 0; mt < 2; mt++) {
                int r = warpM + mt * 16;
                a[mt][0] = As[buf][r + g][k0 + t4];
                a[mt][1] = As[buf][r + g + 8][k0 + t4];
                a[mt][2] = As[buf][r + g][k0 + t4 + 4];
                a[mt][3] = As[buf][r + g + 8][k0 + t4 + 4];
            }
#pragma unroll
            for (int nt = 0; nt < 8; nt++) {
                b[nt][0] = Bs[buf][k0 + t4][warpN + nt * 8 + g];
                b[nt][1] = Bs[buf][k0 + t4 + 4][warpN + nt * 8 + g];
            }
#pragma unroll
            for (int mt = 0; mt < 2; mt++)
#pragma unroll
                for (int nt = 0; nt < 8; nt++) mma_tf32(acc[mt][nt], a[mt], b[nt]);
        }
        __syncthreads();
    }
#pragma unroll
    for (int mt = 0; mt < 2; mt++) {
#pragma unroll
        for (int nt = 0; nt < 8; nt++) {
            int col = nb + warpN + nt * 8 + t4 * 2;
            int r0 = mb + warpM + mt * 16 + g, r1 = r0 + 8;
            if (r0 < NN) {
                float2 x = *(const float2*)&X[(size_t)r0 * FDIM + col];
                float2 o = {x.x - acc[mt][nt][0], x.y - acc[mt][nt][1]};
                *(float2*)&pf[(size_t)r0 * FDIM + col] = o;
            }
            if (r1 < NN) {
                float2 x = *(const float2*)&X[(size_t)r1 * FDIM + col];
                float2 o = {x.x - acc[mt][nt][2], x.y - acc[mt][nt][3]};
                *(float2*)&pf[(size_t)r1 * FDIM + col] = o;
            }
        }
    }
}

// GEMM3: gate = sigmoid(pf@G + b); out = gate*X + (1-gate)*pf. BM=128, BN=128, BK=32, K=384.
__global__ __launch_bounds__(256) void k_gemm3t(const float* __restrict__ G_e,
                                                const float* __restrict__ G_r,
                                                const float* __restrict__ bias_e,
                                                const float* __restrict__ bias_r,
                                                float* __restrict__ out) {
    __shared__ unsigned As[2][128][36];
    __shared__ unsigned Bs[2][32][136];
    int dual = blockIdx.z;
    int mb = blockIdx.x * 128, nb = blockIdx.y * 128;
    const float* X = dual ? g_outr : g_oute;
    const float* G = dual ? G_r : G_e;
    const float* bias = dual ? bias_r : bias_e;
    const float* pf = g_pf + (size_t)dual * NN * FDIM;
    int tid = threadIdx.x, lane = tid & 31, wid = tid >> 5;
    int g = lane >> 2, t4 = lane & 3;
    int warpM = (wid & 3) * 32, warpN = (wid >> 2) * 64;

    int arow = tid >> 3, akq = (tid & 7) * 4;
    int bk = tid >> 5, bcq = (tid & 31) * 4;

    auto loadTiles = [&](int buf, int kc) {
#pragma unroll
        for (int i = 0; i < 4; i++) {
            int row = arow + i * 32;
            int gr = min(mb + row, NN - 1);
            CP16(smemA(&As[buf][row][akq]), &pf[(size_t)gr * FDIM + kc + akq]);
        }
#pragma unroll
        for (int i = 0; i < 4; i++) {
            int k = bk + i * 8;
            CP16(smemA(&Bs[buf][k][bcq]), &G[(size_t)(kc + k) * FDIM + nb + bcq]);
        }
        CPCOMMIT();
    };

    float acc[2][8][4] = {};
    loadTiles(0, 0);
    const int NT = FDIM / 32;  // 12
    for (int t = 0; t < NT; t++) {
        int buf = t & 1;
        if (t + 1 < NT) { loadTiles(buf ^ 1, (t + 1) * 32); CPWAIT1(); }
        else CPWAIT0();
        __syncthreads();
#pragma unroll
        for (int ks = 0; ks < 4; ks++) {
            int k0 = ks * 8;
            unsigned a[2][4], b[8][2];
#pragma unroll
            for (int mt = 0; mt < 2; mt++) {
                int r = warpM + mt * 16;
                a[mt][0] = As[buf][r + g][k0 + t4];
                a[mt][1] = As[buf][r + g + 8][k0 + t4];
                a[mt][2] = As[buf][r + g][k0 + t4 + 4];
                a[mt][3] = As[buf][r + g + 8][k0 + t4 + 4];
            }
#pragma unroll
            for (int nt = 0; nt < 8; nt++) {
                b[nt][0] = Bs[buf][k0 + t4][warpN + nt * 8 + g];
                b[nt][1] = Bs[buf][k0 + t4 + 4][warpN + nt * 8 + g];
            }
#pragma unroll
            for (int mt = 0; mt < 2; mt++)
#pragma unroll
                for (int nt = 0; nt < 8; nt++) mma_tf32(acc[mt][nt], a[mt], b[nt]);
        }
        __syncthreads();
    }
#pragma unroll
    for (int mt = 0; mt < 2; mt++) {
#pragma unroll
        for (int nt = 0; nt < 8; nt++) {
            int col = nb + warpN + nt * 8 + t4 * 2;
            float b0 = bias[col], b1 = bias[col + 1];
            int r0 = mb + warpM + mt * 16 + g, r1 = r0 + 8;
            if (r0 < NN) {
                float g0 = 1.f / (1.f + expf(-(acc[mt][nt][0] + b0)));
                float g1 = 1.f / (1.f + expf(-(acc[mt][nt][1] + b1)));
                float2 x = *(const float2*)&X[(size_t)r0 * FDIM + col];
                float2 p = *(const float2*)&pf[(size_t)r0 * FDIM + col];
                float2 o = {g0 * x.x + (1.f - g0) * p.x, g1 * x.y + (1.f - g1) * p.y};
                *(float2*)&out[(size_t)r0 * (2 * FDIM) + dual * FDIM + col] = o;
            }
            if (r1 < NN) {
                float g0 = 1.f / (1.f + expf(-(acc[mt][nt][2] + b0)));
                float g1 = 1.f / (1.f + expf(-(acc[mt][nt][3] + b1)));
                float2 x = *(const float2*)&X[(size_t)r1 * FDIM + col];
                float2 p = *(const float2*)&pf[(size_t)r1 * FDIM + col];
                float2 o = {g0 * x.x + (1.f - g0) * p.x, g1 * x.y + (1.f - g1) * p.y};
                *(float2*)&out[(size_t)r1 * (2 * FDIM) + dual * FDIM + col] = o;
            }
        }
    }
}

// ---------------- launch ----------------
extern "C" void kernel_launch(void* const* d_in, const int* in_sizes, int n_in,
                              void* d_out, int out_size) {
    const float* ent     = (const float*)d_in[0];
    const float* rel     = (const float*)d_in[1];
    const int*   esrc    = (const int*)d_in[2];
    const int*   edst    = (const int*)d_in[3];
    const int*   erel    = (const int*)d_in[4];
    const float* attn_e  = (const float*)d_in[5];
    const float* gate_e  = (const float*)d_in[6];
    const float* proxy_e = (const float*)d_in[7];
    const float* bias_e  = (const float*)d_in[8];
    const float* attn_r  = (const float*)d_in[9];
    const float* gate_r  = (const float*)d_in[10];
    const float* proxy_r = (const float*)d_in[11];
    const float* bias_r  = (const float*)d_in[12];
    float* out = (float*)d_out;

    k_zero<<<196, 256>>>();
    k_hist<<<3125, 256>>>(edst);
    k_scan<<<1, 1024>>>();
    k_scatter<<<3125, 256>>>(esrc, edst, erel);
    k_relnorm<<<RR, FF>>>(rel, attn_e, attn_r);
    k_proxyn<<<128, FDIM>>>(proxy_e, proxy_r);
    k_init<<<6250, 256>>>(ent, rel);
    k_layer<<<6250, 256>>>(0);
    k_layer<<<6250, 256>>>(1);
    k_invnorm<<<12500, 256>>>();
    k_gemm1t<<<dim3(391, 1, 2), 256>>>();
    k_gemm2t<<<dim3(391, 3, 2), 256>>>(proxy_e, proxy_r);
    k_gemm3t<<<dim3(391, 3, 2), 256>>>(gate_e, gate_r, bias_e, bias_r, out);
}